// round 1
// baseline (speedup 1.0000x reference)
#include <cuda_runtime.h>
#include <cstdint>

#define BATCH   8
#define SEQ     512
#define DIM     1024
#define HEADS   16
#define HD      64
#define NPATCH  196
#define MROWS   (BATCH*SEQ)     /* 4096 */
#define BH      (BATCH*HEADS)   /* 128  */

// ---------------- scratch (device globals: allocation-free) ----------------
__device__ float g_q  [(size_t)BH*SEQ*HD];      // [B,H,S,hd]
__device__ float g_k  [(size_t)BH*SEQ*HD];
__device__ float g_v  [(size_t)BH*SEQ*HD];
__device__ float g_sc [(size_t)BH*SEQ*SEQ];     // [B,H,S,S] scores->probs
__device__ float g_ctx[(size_t)MROWS*DIM];      // [B,S,D]

__device__ __forceinline__ float neg_inf() { return __int_as_float(0xff800000); }

// ---------------------------------------------------------------------------
// Shared 128x128 A*B^T mainloop. A:[*,lda] rows m, B:[*,ldb] rows n, both with
// contiguous K. BK=8, 256 threads, 8x8 accumulators per thread.
// ---------------------------------------------------------------------------
__device__ __forceinline__ void mm128x128_abt(
    const float* __restrict__ Ablk,   // &A[blockRow0 * lda]
    const float* __restrict__ Bblk,   // &B[blockCol0 * ldb]
    int lda, int ldb, int K,
    float (&acc)[8][8])
{
    __shared__ float As[8][128];
    __shared__ float Bs[8][128];
    const int tid = threadIdx.x;
    const int row = tid >> 1;             // 0..127
    const int seg = (tid & 1) << 2;       // 0 or 4
    const int ty  = tid >> 4;             // 0..15
    const int tx  = tid & 15;             // 0..15
    const int m0  = ty << 3;
    const int n0  = tx << 3;

    for (int kt = 0; kt < K; kt += 8) {
        float4 av = *reinterpret_cast<const float4*>(Ablk + (size_t)row * lda + kt + seg);
        float4 bv = *reinterpret_cast<const float4*>(Bblk + (size_t)row * ldb + kt + seg);
        __syncthreads();   // previous tile fully consumed
        As[seg+0][row] = av.x; As[seg+1][row] = av.y;
        As[seg+2][row] = av.z; As[seg+3][row] = av.w;
        Bs[seg+0][row] = bv.x; Bs[seg+1][row] = bv.y;
        Bs[seg+2][row] = bv.z; Bs[seg+3][row] = bv.w;
        __syncthreads();
        #pragma unroll
        for (int kk = 0; kk < 8; ++kk) {
            float4 a0 = *reinterpret_cast<const float4*>(&As[kk][m0]);
            float4 a1 = *reinterpret_cast<const float4*>(&As[kk][m0 + 4]);
            float4 b0 = *reinterpret_cast<const float4*>(&Bs[kk][n0]);
            float4 b1 = *reinterpret_cast<const float4*>(&Bs[kk][n0 + 4]);
            float ra[8] = {a0.x,a0.y,a0.z,a0.w,a1.x,a1.y,a1.z,a1.w};
            float rb[8] = {b0.x,b0.y,b0.z,b0.w,b1.x,b1.y,b1.z,b1.w};
            #pragma unroll
            for (int i = 0; i < 8; ++i)
                #pragma unroll
                for (int j = 0; j < 8; ++j)
                    acc[i][j] = fmaf(ra[i], rb[j], acc[i][j]);
        }
    }
}

// ---------------------------------------------------------------------------
// 1) fused QKV projection: y = x @ W^T, scattered into [B,H,S,hd]
//    grid (DIM/128=8, MROWS/128=32, 3), 256 threads
// ---------------------------------------------------------------------------
__global__ __launch_bounds__(256) void qkv_kernel(
    const float* __restrict__ x,
    const float* __restrict__ wq,
    const float* __restrict__ wk,
    const float* __restrict__ wv)
{
    const float* W  = (blockIdx.z == 0) ? wq : (blockIdx.z == 1) ? wk : wv;
    float*       dst = (blockIdx.z == 0) ? g_q : (blockIdx.z == 1) ? g_k : g_v;

    float acc[8][8] = {};
    mm128x128_abt(x + (size_t)blockIdx.y * 128 * DIM,
                  W + (size_t)blockIdx.x * 128 * DIM,
                  DIM, DIM, DIM, acc);

    const int tid = threadIdx.x, ty = tid >> 4, tx = tid & 15;
    #pragma unroll
    for (int i = 0; i < 8; ++i) {
        int m = blockIdx.y * 128 + ty * 8 + i;
        int b = m >> 9, s = m & 511;
        #pragma unroll
        for (int j = 0; j < 8; ++j) {
            int n = blockIdx.x * 128 + tx * 8 + j;
            int h = n >> 6, d = n & 63;
            dst[(((size_t)(b * HEADS + h) * SEQ) + s) * HD + d] = acc[i][j];
        }
    }
}

// ---------------------------------------------------------------------------
// 2) scores = (Q K^T) * 1/sqrt(hd), prefix-LM mask fused (masked -> -inf)
//    grid (SEQ/128=4, SEQ/128=4, BH=128), 256 threads
// ---------------------------------------------------------------------------
__global__ __launch_bounds__(256) void scores_kernel()
{
    const int bh = blockIdx.z;
    const float* Q  = g_q + (size_t)bh * SEQ * HD;
    const float* Kp = g_k + (size_t)bh * SEQ * HD;

    float acc[8][8] = {};
    mm128x128_abt(Q  + (size_t)blockIdx.y * 128 * HD,
                  Kp + (size_t)blockIdx.x * 128 * HD,
                  HD, HD, HD, acc);

    float* out = g_sc + (size_t)bh * SEQ * SEQ;
    const int tid = threadIdx.x, ty = tid >> 4, tx = tid & 15;
    #pragma unroll
    for (int i = 0; i < 8; ++i) {
        int q = blockIdx.y * 128 + ty * 8 + i;
        #pragma unroll
        for (int j = 0; j < 8; ++j) {
            int k = blockIdx.x * 128 + tx * 8 + j;
            bool ok = (q < NPATCH) ? (k < NPATCH) : (k <= q);
            out[(size_t)q * SEQ + k] = ok ? acc[i][j] * 0.125f : neg_inf();
        }
    }
}

// ---------------------------------------------------------------------------
// 3) row softmax over [BH*SEQ, SEQ], in place. One warp per row.
//    grid (BH*SEQ/8 = 8192), 256 threads
// ---------------------------------------------------------------------------
__global__ __launch_bounds__(256) void softmax_kernel()
{
    const int warp = threadIdx.x >> 5, lane = threadIdx.x & 31;
    const size_t row = (size_t)blockIdx.x * 8 + warp;
    float* p = g_sc + row * SEQ;

    float v[16];
    float mx = neg_inf();
    #pragma unroll
    for (int t = 0; t < 16; ++t) { v[t] = p[lane + t * 32]; mx = fmaxf(mx, v[t]); }
    #pragma unroll
    for (int o = 16; o; o >>= 1) mx = fmaxf(mx, __shfl_xor_sync(0xffffffffu, mx, o));

    float s = 0.f;
    #pragma unroll
    for (int t = 0; t < 16; ++t) { v[t] = __expf(v[t] - mx); s += v[t]; }
    #pragma unroll
    for (int o = 16; o; o >>= 1) s += __shfl_xor_sync(0xffffffffu, s, o);

    const float inv = __frcp_rn(s);
    #pragma unroll
    for (int t = 0; t < 16; ++t) p[lane + t * 32] = v[t] * inv;
}

// ---------------------------------------------------------------------------
// 4) ctx = P @ V per (b,h). A[512,512] * B[512,64] (standard A*B).
//    Tile 128x64, BK=16, 256 threads, 8x4 per thread.
//    grid (1, SEQ/128=4, BH=128)
// ---------------------------------------------------------------------------
__global__ __launch_bounds__(256) void pv_kernel()
{
    const int bh = blockIdx.z;
    const float* P = g_sc + (size_t)bh * SEQ * SEQ + (size_t)blockIdx.y * 128 * SEQ;
    const float* V = g_v  + (size_t)bh * SEQ * HD;

    __shared__ float Ps[16][128];
    __shared__ float Vs[16][64];

    const int tid = threadIdx.x;
    const int ty = tid >> 4, tx = tid & 15;
    const int m0 = ty << 3, n0 = tx << 2;
    float acc[8][4] = {};

    for (int kt = 0; kt < SEQ; kt += 16) {
        // P tile: 128 rows x 16 k = 512 float4, 2 per thread
        float4 pv[2];
        #pragma unroll
        for (int l = 0; l < 2; ++l) {
            int id = tid + l * 256;
            int prow = id >> 2, pk = (id & 3) << 2;
            pv[l] = *reinterpret_cast<const float4*>(P + (size_t)prow * SEQ + kt + pk);
        }
        // V tile: 16 k rows x 64 cols = 256 float4, 1 per thread
        int vk = tid >> 4, vc = (tid & 15) << 2;
        float4 vv = *reinterpret_cast<const float4*>(V + (size_t)(kt + vk) * HD + vc);

        __syncthreads();
        #pragma unroll
        for (int l = 0; l < 2; ++l) {
            int id = tid + l * 256;
            int prow = id >> 2, pk = (id & 3) << 2;
            Ps[pk+0][prow] = pv[l].x; Ps[pk+1][prow] = pv[l].y;
            Ps[pk+2][prow] = pv[l].z; Ps[pk+3][prow] = pv[l].w;
        }
        *reinterpret_cast<float4*>(&Vs[vk][vc]) = vv;
        __syncthreads();

        #pragma unroll
        for (int kk = 0; kk < 16; ++kk) {
            float4 a0 = *reinterpret_cast<const float4*>(&Ps[kk][m0]);
            float4 a1 = *reinterpret_cast<const float4*>(&Ps[kk][m0 + 4]);
            float4 b  = *reinterpret_cast<const float4*>(&Vs[kk][n0]);
            float ra[8] = {a0.x,a0.y,a0.z,a0.w,a1.x,a1.y,a1.z,a1.w};
            float rb[4] = {b.x,b.y,b.z,b.w};
            #pragma unroll
            for (int i = 0; i < 8; ++i)
                #pragma unroll
                for (int j = 0; j < 4; ++j)
                    acc[i][j] = fmaf(ra[i], rb[j], acc[i][j]);
        }
    }

    const int b = bh >> 4, h = bh & 15;
    #pragma unroll
    for (int i = 0; i < 8; ++i) {
        int q = blockIdx.y * 128 + m0 + i;
        float* dst = g_ctx + ((size_t)(b * SEQ + q) * DIM) + h * HD + n0;
        #pragma unroll
        for (int j = 0; j < 4; ++j) dst[j] = acc[i][j];
    }
}

// ---------------------------------------------------------------------------
// 5) out = ctx @ w_o^T + b_o.  grid (8, 32), 256 threads
// ---------------------------------------------------------------------------
__global__ __launch_bounds__(256) void out_kernel(
    const float* __restrict__ wo,
    const float* __restrict__ bo,
    float* __restrict__ out)
{
    float acc[8][8] = {};
    mm128x128_abt(g_ctx + (size_t)blockIdx.y * 128 * DIM,
                  wo    + (size_t)blockIdx.x * 128 * DIM,
                  DIM, DIM, DIM, acc);

    const int tid = threadIdx.x, ty = tid >> 4, tx = tid & 15;
    #pragma unroll
    for (int i = 0; i < 8; ++i) {
        int m = blockIdx.y * 128 + ty * 8 + i;
        #pragma unroll
        for (int j = 0; j < 8; ++j) {
            int n = blockIdx.x * 128 + tx * 8 + j;
            out[(size_t)m * DIM + n] = acc[i][j] + bo[n];
        }
    }
}

// ---------------------------------------------------------------------------
extern "C" void kernel_launch(void* const* d_in, const int* in_sizes, int n_in,
                              void* d_out, int out_size)
{
    const float* x  = (const float*)d_in[0];
    const float* wq = (const float*)d_in[1];
    const float* wk = (const float*)d_in[2];
    const float* wv = (const float*)d_in[3];
    const float* wo = (const float*)d_in[4];
    const float* bo = (const float*)d_in[5];
    float* out = (float*)d_out;

    qkv_kernel   <<<dim3(DIM/128, MROWS/128, 3), 256>>>(x, wq, wk, wv);
    scores_kernel<<<dim3(SEQ/128, SEQ/128, BH), 256>>>();
    softmax_kernel<<<(BH*SEQ)/8, 256>>>();
    pv_kernel    <<<dim3(1, SEQ/128, BH), 256>>>();
    out_kernel   <<<dim3(DIM/128, MROWS/128), 256>>>(wo, bo, out);
}

// round 2
// speedup vs baseline: 1.8576x; 1.8576x over previous
#include <cuda_runtime.h>
#include <cuda_bf16.h>
#include <cstdint>

#define BATCH   8
#define SEQ     512
#define DIM     1024
#define HEADS   16
#define HD      64
#define NPATCH  196
#define MROWS   (BATCH*SEQ)     /* 4096 */
#define BH      (BATCH*HEADS)   /* 128  */

// ---------------- scratch (device globals: allocation-free) ----------------
__device__ float g_q  [(size_t)BH*SEQ*HD];      // [B,H,S,hd] fp32
__device__ float g_k  [(size_t)BH*SEQ*HD];
__device__ float g_v  [(size_t)BH*SEQ*HD];
__device__ float g_sc [(size_t)BH*SEQ*SEQ];     // [B,H,S,S] scores->probs
__device__ float g_ctx[(size_t)MROWS*DIM];      // [B,S,D]

// split-bf16 operands
__device__ __nv_bfloat16 g_xh [(size_t)MROWS*DIM];
__device__ __nv_bfloat16 g_xl [(size_t)MROWS*DIM];
__device__ __nv_bfloat16 g_wh [(size_t)3*DIM*DIM];   // wq,wk,wv
__device__ __nv_bfloat16 g_wl [(size_t)3*DIM*DIM];
__device__ __nv_bfloat16 g_woh[(size_t)DIM*DIM];
__device__ __nv_bfloat16 g_wol[(size_t)DIM*DIM];
__device__ __nv_bfloat16 g_ch [(size_t)MROWS*DIM];   // ctx split
__device__ __nv_bfloat16 g_cl [(size_t)MROWS*DIM];

__device__ __forceinline__ float neg_inf() { return __int_as_float(0xff800000); }

// ===========================================================================
//  split helpers
// ===========================================================================
__device__ __forceinline__ void split4(float4 v, __nv_bfloat16* hi, __nv_bfloat16* lo, size_t i4)
{
    __nv_bfloat16 h0 = __float2bfloat16(v.x);
    __nv_bfloat16 h1 = __float2bfloat16(v.y);
    __nv_bfloat16 h2 = __float2bfloat16(v.z);
    __nv_bfloat16 h3 = __float2bfloat16(v.w);
    __nv_bfloat16 l0 = __float2bfloat16(v.x - __bfloat162float(h0));
    __nv_bfloat16 l1 = __float2bfloat16(v.y - __bfloat162float(h1));
    __nv_bfloat16 l2 = __float2bfloat16(v.z - __bfloat162float(h2));
    __nv_bfloat16 l3 = __float2bfloat16(v.w - __bfloat162float(h3));
    ((__nv_bfloat162*)hi)[i4*2+0] = __nv_bfloat162(h0, h1);
    ((__nv_bfloat162*)hi)[i4*2+1] = __nv_bfloat162(h2, h3);
    ((__nv_bfloat162*)lo)[i4*2+0] = __nv_bfloat162(l0, l1);
    ((__nv_bfloat162*)lo)[i4*2+1] = __nv_bfloat162(l2, l3);
}

__global__ __launch_bounds__(256) void split_x(const float* __restrict__ x)
{
    size_t i = (size_t)blockIdx.x * 256 + threadIdx.x;   // float4 index
    float4 v = ((const float4*)x)[i];
    split4(v, g_xh, g_xl, i);
}

__global__ __launch_bounds__(256) void split_w(const float* __restrict__ wq,
                                               const float* __restrict__ wk,
                                               const float* __restrict__ wv,
                                               const float* __restrict__ wo)
{
    int seg = blockIdx.y;
    const float* src = (seg == 0) ? wq : (seg == 1) ? wk : (seg == 2) ? wv : wo;
    __nv_bfloat16* hi = (seg < 3) ? g_wh + (size_t)seg * DIM * DIM : g_woh;
    __nv_bfloat16* lo = (seg < 3) ? g_wl + (size_t)seg * DIM * DIM : g_wol;
    size_t i = (size_t)blockIdx.x * 256 + threadIdx.x;
    float4 v = ((const float4*)src)[i];
    split4(v, hi, lo, i);
}

__global__ __launch_bounds__(256) void split_ctx()
{
    size_t i = (size_t)blockIdx.x * 256 + threadIdx.x;
    float4 v = ((const float4*)g_ctx)[i];
    split4(v, g_ch, g_cl, i);
}

// ===========================================================================
//  split-bf16 3-term MMA GEMM:  C[128,128] += Ah*Bh^T + Ah*Bl^T + Al*Bh^T
//  A: [M,1024] bf16 (hi/lo), B: [N,1024] bf16 (hi/lo), K contiguous.
//  256 threads, 8 warps (2 M x 4 N), warp tile 64x32, mma m16n8k16.
// ===========================================================================
#define BK       32
#define PAD      40                      /* row stride in bf16 elems (80B)   */
#define TE       (128*PAD)               /* tile elems                        */
#define NKT      (DIM/BK)                /* 32 K-tiles                        */
#define SMEM_BYTES (2*4*TE*2)            /* 2 stages * 4 tiles * bf16 = 81920 */

__device__ __forceinline__ uint32_t smem_u32(const void* p)
{ return (uint32_t)__cvta_generic_to_shared(p); }

__device__ __forceinline__ void cp_async16(uint32_t s, const void* g)
{ asm volatile("cp.async.cg.shared.global [%0], [%1], 16;\n" :: "r"(s), "l"(g)); }

__device__ __forceinline__ uint32_t ld2(const __nv_bfloat16* p)
{ return *reinterpret_cast<const uint32_t*>(p); }

__device__ __forceinline__ void mma16(float* c, const uint32_t* a, const uint32_t* b)
{
    asm volatile(
        "mma.sync.aligned.m16n8k16.row.col.f32.bf16.bf16.f32 "
        "{%0,%1,%2,%3},{%4,%5,%6,%7},{%8,%9},{%0,%1,%2,%3};"
        : "+f"(c[0]), "+f"(c[1]), "+f"(c[2]), "+f"(c[3])
        : "r"(a[0]), "r"(a[1]), "r"(a[2]), "r"(a[3]), "r"(b[0]), "r"(b[1]));
}

__device__ __forceinline__ void gemm3term(
    const __nv_bfloat16* __restrict__ Ah, const __nv_bfloat16* __restrict__ Al,
    const __nv_bfloat16* __restrict__ Bh, const __nv_bfloat16* __restrict__ Bl,
    __nv_bfloat16* sm, float (&acc)[4][4][4])
{
    const int tid  = threadIdx.x;
    const int warp = tid >> 5, lane = tid & 31;
    const int g    = lane >> 2, t2 = (lane & 3) << 1;
    const int wm0  = (warp & 1) << 6;     // 0 / 64
    const int wn0  = (warp >> 1) << 5;    // 0..96
    const int crow = tid >> 2, cu = tid & 3;
    const __nv_bfloat16* srcs[4] = {Ah, Al, Bh, Bl};

    // ---- stage loader (cp.async) ----
    auto load_stage = [&](int kt, int s) {
        #pragma unroll
        for (int t = 0; t < 4; ++t) {
            const __nv_bfloat16* src = srcs[t];
            __nv_bfloat16* dst = sm + (size_t)(s * 4 + t) * TE;
            cp_async16(smem_u32(dst + crow * PAD + cu * 8),
                       src + (size_t)crow * DIM + kt * BK + cu * 8);
            cp_async16(smem_u32(dst + (crow + 64) * PAD + cu * 8),
                       src + (size_t)(crow + 64) * DIM + kt * BK + cu * 8);
        }
    };

    load_stage(0, 0);
    asm volatile("cp.async.commit_group;\n" ::: "memory");

    for (int kt = 0; kt < NKT; ++kt) {
        const int cur = kt & 1;
        if (kt + 1 < NKT) {
            load_stage(kt + 1, cur ^ 1);
            asm volatile("cp.async.commit_group;\n" ::: "memory");
            asm volatile("cp.async.wait_group 1;\n" ::: "memory");
        } else {
            asm volatile("cp.async.wait_group 0;\n" ::: "memory");
        }
        __syncthreads();

        const __nv_bfloat16* sAh = sm + (size_t)(cur * 4 + 0) * TE;
        const __nv_bfloat16* sAl = sm + (size_t)(cur * 4 + 1) * TE;
        const __nv_bfloat16* sBh = sm + (size_t)(cur * 4 + 2) * TE;
        const __nv_bfloat16* sBl = sm + (size_t)(cur * 4 + 3) * TE;

        #pragma unroll
        for (int ks = 0; ks < BK; ks += 16) {
            uint32_t bh[4][2], bl[4][2], a[4][4];
            #pragma unroll
            for (int j = 0; j < 4; ++j) {
                int r = (wn0 + j * 8 + g) * PAD + ks + t2;
                bh[j][0] = ld2(sBh + r); bh[j][1] = ld2(sBh + r + 8);
                bl[j][0] = ld2(sBl + r); bl[j][1] = ld2(sBl + r + 8);
            }
            #pragma unroll
            for (int i = 0; i < 4; ++i) {
                int r = (wm0 + i * 16 + g) * PAD + ks + t2;
                a[i][0] = ld2(sAh + r);           a[i][1] = ld2(sAh + r + 8 * PAD);
                a[i][2] = ld2(sAh + r + 8);       a[i][3] = ld2(sAh + r + 8 * PAD + 8);
            }
            #pragma unroll
            for (int i = 0; i < 4; ++i)
                #pragma unroll
                for (int j = 0; j < 4; ++j) mma16(acc[i][j], a[i], bh[j]);
            #pragma unroll
            for (int i = 0; i < 4; ++i)
                #pragma unroll
                for (int j = 0; j < 4; ++j) mma16(acc[i][j], a[i], bl[j]);
            #pragma unroll
            for (int i = 0; i < 4; ++i) {
                int r = (wm0 + i * 16 + g) * PAD + ks + t2;
                a[i][0] = ld2(sAl + r);           a[i][1] = ld2(sAl + r + 8 * PAD);
                a[i][2] = ld2(sAl + r + 8);       a[i][3] = ld2(sAl + r + 8 * PAD + 8);
            }
            #pragma unroll
            for (int i = 0; i < 4; ++i)
                #pragma unroll
                for (int j = 0; j < 4; ++j) mma16(acc[i][j], a[i], bh[j]);
        }
        __syncthreads();
    }
}

// ---- 1) QKV projection via split-bf16 MMA, scatter into [B,H,S,hd] fp32 ----
__global__ __launch_bounds__(256) void qkv_mma()
{
    extern __shared__ __nv_bfloat16 sm[];
    const int z = blockIdx.z;
    const __nv_bfloat16* Ah = g_xh + (size_t)blockIdx.y * 128 * DIM;
    const __nv_bfloat16* Al = g_xl + (size_t)blockIdx.y * 128 * DIM;
    const __nv_bfloat16* Bh = g_wh + (size_t)z * DIM * DIM + (size_t)blockIdx.x * 128 * DIM;
    const __nv_bfloat16* Bl = g_wl + (size_t)z * DIM * DIM + (size_t)blockIdx.x * 128 * DIM;
    float* dst = (z == 0) ? g_q : (z == 1) ? g_k : g_v;

    float acc[4][4][4] = {};
    gemm3term(Ah, Al, Bh, Bl, sm, acc);

    const int warp = threadIdx.x >> 5, lane = threadIdx.x & 31;
    const int g = lane >> 2, t2 = (lane & 3) << 1;
    const int wm0 = (warp & 1) << 6, wn0 = (warp >> 1) << 5;
    #pragma unroll
    for (int i = 0; i < 4; ++i)
        #pragma unroll
        for (int j = 0; j < 4; ++j)
            #pragma unroll
            for (int r = 0; r < 4; ++r) {
                int m = blockIdx.y * 128 + wm0 + i * 16 + g + ((r >= 2) ? 8 : 0);
                int n = blockIdx.x * 128 + wn0 + j * 8 + t2 + (r & 1);
                int b = m >> 9, s = m & 511, h = n >> 6, d = n & 63;
                dst[(((size_t)(b * HEADS + h) * SEQ) + s) * HD + d] = acc[i][j][r];
            }
}

// ---- 5) out projection via split-bf16 MMA + bias -------------------------
__global__ __launch_bounds__(256) void out_mma(const float* __restrict__ bo,
                                               float* __restrict__ out)
{
    extern __shared__ __nv_bfloat16 sm[];
    const __nv_bfloat16* Ah = g_ch + (size_t)blockIdx.y * 128 * DIM;
    const __nv_bfloat16* Al = g_cl + (size_t)blockIdx.y * 128 * DIM;
    const __nv_bfloat16* Bh = g_woh + (size_t)blockIdx.x * 128 * DIM;
    const __nv_bfloat16* Bl = g_wol + (size_t)blockIdx.x * 128 * DIM;

    float acc[4][4][4] = {};
    gemm3term(Ah, Al, Bh, Bl, sm, acc);

    const int warp = threadIdx.x >> 5, lane = threadIdx.x & 31;
    const int g = lane >> 2, t2 = (lane & 3) << 1;
    const int wm0 = (warp & 1) << 6, wn0 = (warp >> 1) << 5;
    #pragma unroll
    for (int i = 0; i < 4; ++i)
        #pragma unroll
        for (int j = 0; j < 4; ++j)
            #pragma unroll
            for (int r = 0; r < 4; ++r) {
                int m = blockIdx.y * 128 + wm0 + i * 16 + g + ((r >= 2) ? 8 : 0);
                int n = blockIdx.x * 128 + wn0 + j * 8 + t2 + (r & 1);
                out[(size_t)m * DIM + n] = acc[i][j][r] + bo[n];
            }
}

// ===========================================================================
//  fp32 128x128 A*B^T mainloop (scores) — unchanged from R1
// ===========================================================================
__device__ __forceinline__ void mm128x128_abt(
    const float* __restrict__ Ablk, const float* __restrict__ Bblk,
    int lda, int ldb, int K, float (&acc)[8][8])
{
    __shared__ float As[8][128];
    __shared__ float Bs[8][128];
    const int tid = threadIdx.x;
    const int row = tid >> 1;
    const int seg = (tid & 1) << 2;
    const int ty  = tid >> 4;
    const int tx  = tid & 15;
    const int m0  = ty << 3;
    const int n0  = tx << 3;

    for (int kt = 0; kt < K; kt += 8) {
        float4 av = *reinterpret_cast<const float4*>(Ablk + (size_t)row * lda + kt + seg);
        float4 bv = *reinterpret_cast<const float4*>(Bblk + (size_t)row * ldb + kt + seg);
        __syncthreads();
        As[seg+0][row] = av.x; As[seg+1][row] = av.y;
        As[seg+2][row] = av.z; As[seg+3][row] = av.w;
        Bs[seg+0][row] = bv.x; Bs[seg+1][row] = bv.y;
        Bs[seg+2][row] = bv.z; Bs[seg+3][row] = bv.w;
        __syncthreads();
        #pragma unroll
        for (int kk = 0; kk < 8; ++kk) {
            float4 a0 = *reinterpret_cast<const float4*>(&As[kk][m0]);
            float4 a1 = *reinterpret_cast<const float4*>(&As[kk][m0 + 4]);
            float4 b0 = *reinterpret_cast<const float4*>(&Bs[kk][n0]);
            float4 b1 = *reinterpret_cast<const float4*>(&Bs[kk][n0 + 4]);
            float ra[8] = {a0.x,a0.y,a0.z,a0.w,a1.x,a1.y,a1.z,a1.w};
            float rb[8] = {b0.x,b0.y,b0.z,b0.w,b1.x,b1.y,b1.z,b1.w};
            #pragma unroll
            for (int i = 0; i < 8; ++i)
                #pragma unroll
                for (int j = 0; j < 8; ++j)
                    acc[i][j] = fmaf(ra[i], rb[j], acc[i][j]);
        }
    }
}

// ---- 2) scores = (Q K^T)/8 with prefix-LM mask ----------------------------
__global__ __launch_bounds__(256) void scores_kernel()
{
    const int bh = blockIdx.z;
    const float* Q  = g_q + (size_t)bh * SEQ * HD;
    const float* Kp = g_k + (size_t)bh * SEQ * HD;

    float acc[8][8] = {};
    mm128x128_abt(Q  + (size_t)blockIdx.y * 128 * HD,
                  Kp + (size_t)blockIdx.x * 128 * HD, HD, HD, HD, acc);

    float* out = g_sc + (size_t)bh * SEQ * SEQ;
    const int tid = threadIdx.x, ty = tid >> 4, tx = tid & 15;
    #pragma unroll
    for (int i = 0; i < 8; ++i) {
        int q = blockIdx.y * 128 + ty * 8 + i;
        #pragma unroll
        for (int j = 0; j < 8; ++j) {
            int k = blockIdx.x * 128 + tx * 8 + j;
            bool ok = (q < NPATCH) ? (k < NPATCH) : (k <= q);
            out[(size_t)q * SEQ + k] = ok ? acc[i][j] * 0.125f : neg_inf();
        }
    }
}

// ---- 3) row softmax, warp per row -----------------------------------------
__global__ __launch_bounds__(256) void softmax_kernel()
{
    const int warp = threadIdx.x >> 5, lane = threadIdx.x & 31;
    const size_t row = (size_t)blockIdx.x * 8 + warp;
    float* p = g_sc + row * SEQ;

    float v[16];
    float mx = neg_inf();
    #pragma unroll
    for (int t = 0; t < 16; ++t) { v[t] = p[lane + t * 32]; mx = fmaxf(mx, v[t]); }
    #pragma unroll
    for (int o = 16; o; o >>= 1) mx = fmaxf(mx, __shfl_xor_sync(0xffffffffu, mx, o));

    float s = 0.f;
    #pragma unroll
    for (int t = 0; t < 16; ++t) { v[t] = __expf(v[t] - mx); s += v[t]; }
    #pragma unroll
    for (int o = 16; o; o >>= 1) s += __shfl_xor_sync(0xffffffffu, s, o);

    const float inv = __frcp_rn(s);
    #pragma unroll
    for (int t = 0; t < 16; ++t) p[lane + t * 32] = v[t] * inv;
}

// ---- 4) ctx = P @ V per (b,h) ---------------------------------------------
__global__ __launch_bounds__(256) void pv_kernel()
{
    const int bh = blockIdx.z;
    const float* P = g_sc + (size_t)bh * SEQ * SEQ + (size_t)blockIdx.y * 128 * SEQ;
    const float* V = g_v  + (size_t)bh * SEQ * HD;

    __shared__ float Ps[16][128];
    __shared__ float Vs[16][64];

    const int tid = threadIdx.x;
    const int ty = tid >> 4, tx = tid & 15;
    const int m0 = ty << 3, n0 = tx << 2;
    float acc[8][4] = {};

    for (int kt = 0; kt < SEQ; kt += 16) {
        float4 pv[2];
        #pragma unroll
        for (int l = 0; l < 2; ++l) {
            int id = tid + l * 256;
            int prow = id >> 2, pk = (id & 3) << 2;
            pv[l] = *reinterpret_cast<const float4*>(P + (size_t)prow * SEQ + kt + pk);
        }
        int vk = tid >> 4, vc = (tid & 15) << 2;
        float4 vv = *reinterpret_cast<const float4*>(V + (size_t)(kt + vk) * HD + vc);

        __syncthreads();
        #pragma unroll
        for (int l = 0; l < 2; ++l) {
            int id = tid + l * 256;
            int prow = id >> 2, pk = (id & 3) << 2;
            Ps[pk+0][prow] = pv[l].x; Ps[pk+1][prow] = pv[l].y;
            Ps[pk+2][prow] = pv[l].z; Ps[pk+3][prow] = pv[l].w;
        }
        *reinterpret_cast<float4*>(&Vs[vk][vc]) = vv;
        __syncthreads();

        #pragma unroll
        for (int kk = 0; kk < 16; ++kk) {
            float4 a0 = *reinterpret_cast<const float4*>(&Ps[kk][m0]);
            float4 a1 = *reinterpret_cast<const float4*>(&Ps[kk][m0 + 4]);
            float4 b  = *reinterpret_cast<const float4*>(&Vs[kk][n0]);
            float ra[8] = {a0.x,a0.y,a0.z,a0.w,a1.x,a1.y,a1.z,a1.w};
            float rb[4] = {b.x,b.y,b.z,b.w};
            #pragma unroll
            for (int i = 0; i < 8; ++i)
                #pragma unroll
                for (int j = 0; j < 4; ++j)
                    acc[i][j] = fmaf(ra[i], rb[j], acc[i][j]);
        }
    }

    const int b = bh >> 4, h = bh & 15;
    #pragma unroll
    for (int i = 0; i < 8; ++i) {
        int q = blockIdx.y * 128 + m0 + i;
        float* dst = g_ctx + ((size_t)(b * SEQ + q) * DIM) + h * HD + n0;
        #pragma unroll
        for (int j = 0; j < 4; ++j) dst[j] = acc[i][j];
    }
}

// ===========================================================================
extern "C" void kernel_launch(void* const* d_in, const int* in_sizes, int n_in,
                              void* d_out, int out_size)
{
    const float* x  = (const float*)d_in[0];
    const float* wq = (const float*)d_in[1];
    const float* wk = (const float*)d_in[2];
    const float* wv = (const float*)d_in[3];
    const float* wo = (const float*)d_in[4];
    const float* bo = (const float*)d_in[5];
    float* out = (float*)d_out;

    static bool attr_set = false;
    if (!attr_set) {
        cudaFuncSetAttribute(qkv_mma, cudaFuncAttributeMaxDynamicSharedMemorySize, SMEM_BYTES);
        cudaFuncSetAttribute(out_mma, cudaFuncAttributeMaxDynamicSharedMemorySize, SMEM_BYTES);
        attr_set = true;
    }

    split_x<<<MROWS*DIM/4/256, 256>>>(x);
    split_w<<<dim3(DIM*DIM/4/256, 4), 256>>>(wq, wk, wv, wo);

    qkv_mma<<<dim3(DIM/128, MROWS/128, 3), 256, SMEM_BYTES>>>();
    scores_kernel<<<dim3(SEQ/128, SEQ/128, BH), 256>>>();
    softmax_kernel<<<(BH*SEQ)/8, 256>>>();
    pv_kernel<<<dim3(1, SEQ/128, BH), 256>>>();

    split_ctx<<<MROWS*DIM/4/256, 256>>>();
    out_mma<<<dim3(DIM/128, MROWS/128), 256, SMEM_BYTES>>>(bo, out);
}

// round 3
// speedup vs baseline: 1.9481x; 1.0488x over previous
#include <cuda_runtime.h>
#include <cuda_bf16.h>
#include <cstdint>

#define BATCH   8
#define SEQ     512
#define DIM     1024
#define HEADS   16
#define HD      64
#define NPATCH  196
#define MROWS   (BATCH*SEQ)     /* 4096 */
#define BH      (BATCH*HEADS)   /* 128  */

// ---------------- scratch (device globals: allocation-free) ----------------
__device__ float g_sc [(size_t)BH*SEQ*SEQ];          // fp32 scores
__device__ __nv_bfloat16 g_xh [(size_t)MROWS*DIM];
__device__ __nv_bfloat16 g_xl [(size_t)MROWS*DIM];
__device__ __nv_bfloat16 g_wh [(size_t)3*DIM*DIM];
__device__ __nv_bfloat16 g_wl [(size_t)3*DIM*DIM];
__device__ __nv_bfloat16 g_woh[(size_t)DIM*DIM];
__device__ __nv_bfloat16 g_wol[(size_t)DIM*DIM];
__device__ __nv_bfloat16 g_qh [(size_t)BH*SEQ*HD];   // [B,H,S,hd]
__device__ __nv_bfloat16 g_ql [(size_t)BH*SEQ*HD];
__device__ __nv_bfloat16 g_kh [(size_t)BH*SEQ*HD];
__device__ __nv_bfloat16 g_kl [(size_t)BH*SEQ*HD];
__device__ __nv_bfloat16 g_vh [(size_t)BH*HD*SEQ];   // [B,H,hd,S] (transposed)
__device__ __nv_bfloat16 g_vl [(size_t)BH*HD*SEQ];
__device__ __nv_bfloat16 g_ph [(size_t)BH*SEQ*SEQ];  // probs split
__device__ __nv_bfloat16 g_pl [(size_t)BH*SEQ*SEQ];
__device__ __nv_bfloat16 g_ch [(size_t)MROWS*DIM];   // ctx split [B,S,D]
__device__ __nv_bfloat16 g_cl [(size_t)MROWS*DIM];

__device__ __forceinline__ float neg_inf() { return __int_as_float(0xff800000); }

// ===========================================================================
//  split helpers
// ===========================================================================
__device__ __forceinline__ void split4(float4 v, __nv_bfloat16* hi, __nv_bfloat16* lo, size_t i4)
{
    __nv_bfloat16 h0 = __float2bfloat16(v.x);
    __nv_bfloat16 h1 = __float2bfloat16(v.y);
    __nv_bfloat16 h2 = __float2bfloat16(v.z);
    __nv_bfloat16 h3 = __float2bfloat16(v.w);
    __nv_bfloat16 l0 = __float2bfloat16(v.x - __bfloat162float(h0));
    __nv_bfloat16 l1 = __float2bfloat16(v.y - __bfloat162float(h1));
    __nv_bfloat16 l2 = __float2bfloat16(v.z - __bfloat162float(h2));
    __nv_bfloat16 l3 = __float2bfloat16(v.w - __bfloat162float(h3));
    ((__nv_bfloat162*)hi)[i4*2+0] = __nv_bfloat162(h0, h1);
    ((__nv_bfloat162*)hi)[i4*2+1] = __nv_bfloat162(h2, h3);
    ((__nv_bfloat162*)lo)[i4*2+0] = __nv_bfloat162(l0, l1);
    ((__nv_bfloat162*)lo)[i4*2+1] = __nv_bfloat162(l2, l3);
}

__global__ __launch_bounds__(256) void split_x(const float* __restrict__ x)
{
    size_t i = (size_t)blockIdx.x * 256 + threadIdx.x;
    float4 v = ((const float4*)x)[i];
    split4(v, g_xh, g_xl, i);
}

__global__ __launch_bounds__(256) void split_w(const float* __restrict__ wq,
                                               const float* __restrict__ wk,
                                               const float* __restrict__ wv,
                                               const float* __restrict__ wo)
{
    int seg = blockIdx.y;
    const float* src = (seg == 0) ? wq : (seg == 1) ? wk : (seg == 2) ? wv : wo;
    __nv_bfloat16* hi = (seg < 3) ? g_wh + (size_t)seg * DIM * DIM : g_woh;
    __nv_bfloat16* lo = (seg < 3) ? g_wl + (size_t)seg * DIM * DIM : g_wol;
    size_t i = (size_t)blockIdx.x * 256 + threadIdx.x;
    float4 v = ((const float4*)src)[i];
    split4(v, hi, lo, i);
}

// ===========================================================================
//  common MMA utils
// ===========================================================================
__device__ __forceinline__ uint32_t smem_u32(const void* p)
{ return (uint32_t)__cvta_generic_to_shared(p); }

__device__ __forceinline__ void cp_async16(uint32_t s, const void* g)
{ asm volatile("cp.async.cg.shared.global [%0], [%1], 16;\n" :: "r"(s), "l"(g)); }

__device__ __forceinline__ uint32_t ld2(const __nv_bfloat16* p)
{ return *reinterpret_cast<const uint32_t*>(p); }

__device__ __forceinline__ void mma16(float* c, const uint32_t* a, const uint32_t* b)
{
    asm volatile(
        "mma.sync.aligned.m16n8k16.row.col.f32.bf16.bf16.f32 "
        "{%0,%1,%2,%3},{%4,%5,%6,%7},{%8,%9},{%0,%1,%2,%3};"
        : "+f"(c[0]), "+f"(c[1]), "+f"(c[2]), "+f"(c[3])
        : "r"(a[0]), "r"(a[1]), "r"(a[2]), "r"(a[3]), "r"(b[0]), "r"(b[1]));
}

// ===========================================================================
//  split-bf16 3-term 128x128 GEMM over K=1024 (projections)
// ===========================================================================
#define BK       32
#define PAD      40
#define TE       (128*PAD)
#define NKT      (DIM/BK)
#define SMEM_BYTES (2*4*TE*2)

__device__ __forceinline__ void gemm3term(
    const __nv_bfloat16* __restrict__ Ah, const __nv_bfloat16* __restrict__ Al,
    const __nv_bfloat16* __restrict__ Bh, const __nv_bfloat16* __restrict__ Bl,
    __nv_bfloat16* sm, float (&acc)[4][4][4])
{
    const int tid  = threadIdx.x;
    const int warp = tid >> 5, lane = tid & 31;
    const int g    = lane >> 2, t2 = (lane & 3) << 1;
    const int wm0  = (warp & 1) << 6;
    const int wn0  = (warp >> 1) << 5;
    const int crow = tid >> 2, cu = tid & 3;
    const __nv_bfloat16* srcs[4] = {Ah, Al, Bh, Bl};

    auto load_stage = [&](int kt, int s) {
        #pragma unroll
        for (int t = 0; t < 4; ++t) {
            const __nv_bfloat16* src = srcs[t];
            __nv_bfloat16* dst = sm + (size_t)(s * 4 + t) * TE;
            cp_async16(smem_u32(dst + crow * PAD + cu * 8),
                       src + (size_t)crow * DIM + kt * BK + cu * 8);
            cp_async16(smem_u32(dst + (crow + 64) * PAD + cu * 8),
                       src + (size_t)(crow + 64) * DIM + kt * BK + cu * 8);
        }
    };

    load_stage(0, 0);
    asm volatile("cp.async.commit_group;\n" ::: "memory");

    for (int kt = 0; kt < NKT; ++kt) {
        const int cur = kt & 1;
        if (kt + 1 < NKT) {
            load_stage(kt + 1, cur ^ 1);
            asm volatile("cp.async.commit_group;\n" ::: "memory");
            asm volatile("cp.async.wait_group 1;\n" ::: "memory");
        } else {
            asm volatile("cp.async.wait_group 0;\n" ::: "memory");
        }
        __syncthreads();

        const __nv_bfloat16* sAh = sm + (size_t)(cur * 4 + 0) * TE;
        const __nv_bfloat16* sAl = sm + (size_t)(cur * 4 + 1) * TE;
        const __nv_bfloat16* sBh = sm + (size_t)(cur * 4 + 2) * TE;
        const __nv_bfloat16* sBl = sm + (size_t)(cur * 4 + 3) * TE;

        #pragma unroll
        for (int ks = 0; ks < BK; ks += 16) {
            uint32_t bh[4][2], bl[4][2], a[4][4];
            #pragma unroll
            for (int j = 0; j < 4; ++j) {
                int r = (wn0 + j * 8 + g) * PAD + ks + t2;
                bh[j][0] = ld2(sBh + r); bh[j][1] = ld2(sBh + r + 8);
                bl[j][0] = ld2(sBl + r); bl[j][1] = ld2(sBl + r + 8);
            }
            #pragma unroll
            for (int i = 0; i < 4; ++i) {
                int r = (wm0 + i * 16 + g) * PAD + ks + t2;
                a[i][0] = ld2(sAh + r);     a[i][1] = ld2(sAh + r + 8 * PAD);
                a[i][2] = ld2(sAh + r + 8); a[i][3] = ld2(sAh + r + 8 * PAD + 8);
            }
            #pragma unroll
            for (int i = 0; i < 4; ++i)
                #pragma unroll
                for (int j = 0; j < 4; ++j) mma16(acc[i][j], a[i], bh[j]);
            #pragma unroll
            for (int i = 0; i < 4; ++i)
                #pragma unroll
                for (int j = 0; j < 4; ++j) mma16(acc[i][j], a[i], bl[j]);
            #pragma unroll
            for (int i = 0; i < 4; ++i) {
                int r = (wm0 + i * 16 + g) * PAD + ks + t2;
                a[i][0] = ld2(sAl + r);     a[i][1] = ld2(sAl + r + 8 * PAD);
                a[i][2] = ld2(sAl + r + 8); a[i][3] = ld2(sAl + r + 8 * PAD + 8);
            }
            #pragma unroll
            for (int i = 0; i < 4; ++i)
                #pragma unroll
                for (int j = 0; j < 4; ++j) mma16(acc[i][j], a[i], bh[j]);
        }
        __syncthreads();
    }
}

// ---- 1) QKV projection: Q,K -> split bf16 [B,H,S,hd]; V -> split bf16 [B,H,hd,S]
__global__ __launch_bounds__(256) void qkv_mma()
{
    extern __shared__ __nv_bfloat16 sm[];
    const int z = blockIdx.z;
    const __nv_bfloat16* Ah = g_xh + (size_t)blockIdx.y * 128 * DIM;
    const __nv_bfloat16* Al = g_xl + (size_t)blockIdx.y * 128 * DIM;
    const __nv_bfloat16* Bh = g_wh + (size_t)z * DIM * DIM + (size_t)blockIdx.x * 128 * DIM;
    const __nv_bfloat16* Bl = g_wl + (size_t)z * DIM * DIM + (size_t)blockIdx.x * 128 * DIM;

    float acc[4][4][4] = {};
    gemm3term(Ah, Al, Bh, Bl, sm, acc);

    __nv_bfloat16* hi = (z == 0) ? g_qh : (z == 1) ? g_kh : g_vh;
    __nv_bfloat16* lo = (z == 0) ? g_ql : (z == 1) ? g_kl : g_vl;

    const int warp = threadIdx.x >> 5, lane = threadIdx.x & 31;
    const int g = lane >> 2, t2 = (lane & 3) << 1;
    const int wm0 = (warp & 1) << 6, wn0 = (warp >> 1) << 5;
    #pragma unroll
    for (int i = 0; i < 4; ++i)
        #pragma unroll
        for (int j = 0; j < 4; ++j)
            #pragma unroll
            for (int r = 0; r < 4; ++r) {
                int m = blockIdx.y * 128 + wm0 + i * 16 + g + ((r >= 2) ? 8 : 0);
                int n = blockIdx.x * 128 + wn0 + j * 8 + t2 + (r & 1);
                int b = m >> 9, s = m & 511, h = n >> 6, d = n & 63;
                size_t idx;
                if (z == 2) idx = ((size_t)(b * HEADS + h) * HD + d) * SEQ + s;   // transposed
                else        idx = ((size_t)(b * HEADS + h) * SEQ + s) * HD + d;
                float v = acc[i][j][r];
                __nv_bfloat16 hh = __float2bfloat16(v);
                hi[idx] = hh;
                lo[idx] = __float2bfloat16(v - __bfloat162float(hh));
            }
}

// ===========================================================================
//  2) scores = (Q K^T)/8 via 3-term MMA, mask fused.  grid (kt=4, qt=4, bh=128)
// ===========================================================================
#define PADS 72
#define TES  (128*PADS)

__global__ __launch_bounds__(256) void scores_mma()
{
    extern __shared__ __nv_bfloat16 sms[];
    const int bh = blockIdx.z;
    const int qt = blockIdx.y, kt = blockIdx.x;
    const __nv_bfloat16* Qh = g_qh + ((size_t)bh * SEQ + qt * 128) * HD;
    const __nv_bfloat16* Ql = g_ql + ((size_t)bh * SEQ + qt * 128) * HD;
    const __nv_bfloat16* Kh = g_kh + ((size_t)bh * SEQ + kt * 128) * HD;
    const __nv_bfloat16* Kl = g_kl + ((size_t)bh * SEQ + kt * 128) * HD;

    const int tid = threadIdx.x;
    const __nv_bfloat16* srcs[4] = {Qh, Ql, Kh, Kl};
    #pragma unroll
    for (int t = 0; t < 4; ++t) {
        __nv_bfloat16* dst = sms + (size_t)t * TES;
        #pragma unroll
        for (int c = 0; c < 4; ++c) {
            int idx = tid + c * 256;           // 0..1023
            int row = idx >> 3, chunk = idx & 7;
            cp_async16(smem_u32(dst + row * PADS + chunk * 8),
                       srcs[t] + (size_t)row * HD + chunk * 8);
        }
    }
    asm volatile("cp.async.commit_group;\n" ::: "memory");
    asm volatile("cp.async.wait_group 0;\n" ::: "memory");
    __syncthreads();

    const __nv_bfloat16* sAh = sms + 0 * TES;
    const __nv_bfloat16* sAl = sms + 1 * TES;
    const __nv_bfloat16* sBh = sms + 2 * TES;
    const __nv_bfloat16* sBl = sms + 3 * TES;

    const int warp = tid >> 5, lane = tid & 31;
    const int g = lane >> 2, t2 = (lane & 3) << 1;
    const int wm0 = (warp & 1) << 6, wn0 = (warp >> 1) << 5;

    float acc[4][4][4] = {};
    #pragma unroll
    for (int ks = 0; ks < HD; ks += 16) {
        uint32_t bh2[4][2], bl2[4][2], a[4][4];
        #pragma unroll
        for (int j = 0; j < 4; ++j) {
            int r = (wn0 + j * 8 + g) * PADS + ks + t2;
            bh2[j][0] = ld2(sBh + r); bh2[j][1] = ld2(sBh + r + 8);
            bl2[j][0] = ld2(sBl + r); bl2[j][1] = ld2(sBl + r + 8);
        }
        #pragma unroll
        for (int i = 0; i < 4; ++i) {
            int r = (wm0 + i * 16 + g) * PADS + ks + t2;
            a[i][0] = ld2(sAh + r);     a[i][1] = ld2(sAh + r + 8 * PADS);
            a[i][2] = ld2(sAh + r + 8); a[i][3] = ld2(sAh + r + 8 * PADS + 8);
        }
        #pragma unroll
        for (int i = 0; i < 4; ++i)
            #pragma unroll
            for (int j = 0; j < 4; ++j) mma16(acc[i][j], a[i], bh2[j]);
        #pragma unroll
        for (int i = 0; i < 4; ++i)
            #pragma unroll
            for (int j = 0; j < 4; ++j) mma16(acc[i][j], a[i], bl2[j]);
        #pragma unroll
        for (int i = 0; i < 4; ++i) {
            int r = (wm0 + i * 16 + g) * PADS + ks + t2;
            a[i][0] = ld2(sAl + r);     a[i][1] = ld2(sAl + r + 8 * PADS);
            a[i][2] = ld2(sAl + r + 8); a[i][3] = ld2(sAl + r + 8 * PADS + 8);
        }
        #pragma unroll
        for (int i = 0; i < 4; ++i)
            #pragma unroll
            for (int j = 0; j < 4; ++j) mma16(acc[i][j], a[i], bh2[j]);
    }

    float* out = g_sc + (size_t)bh * SEQ * SEQ;
    #pragma unroll
    for (int i = 0; i < 4; ++i)
        #pragma unroll
        for (int j = 0; j < 4; ++j)
            #pragma unroll
            for (int r = 0; r < 4; ++r) {
                int q = qt * 128 + wm0 + i * 16 + g + ((r >= 2) ? 8 : 0);
                int k = kt * 128 + wn0 + j * 8 + t2 + (r & 1);
                bool ok = (q < NPATCH) ? (k < NPATCH) : (k <= q);
                out[(size_t)q * SEQ + k] = ok ? acc[i][j][r] * 0.125f : neg_inf();
            }
}

// ===========================================================================
//  3) row softmax -> split bf16 probs. warp per row, contiguous 16-col lanes.
// ===========================================================================
__global__ __launch_bounds__(256) void softmax_kernel()
{
    const int warp = threadIdx.x >> 5, lane = threadIdx.x & 31;
    const size_t row = (size_t)blockIdx.x * 8 + warp;
    const float* p = g_sc + row * SEQ + lane * 16;

    float v[16];
    float mx = neg_inf();
    #pragma unroll
    for (int c = 0; c < 4; ++c) {
        float4 lv = ((const float4*)p)[c];
        v[4*c+0] = lv.x; v[4*c+1] = lv.y; v[4*c+2] = lv.z; v[4*c+3] = lv.w;
    }
    #pragma unroll
    for (int t = 0; t < 16; ++t) mx = fmaxf(mx, v[t]);
    #pragma unroll
    for (int o = 16; o; o >>= 1) mx = fmaxf(mx, __shfl_xor_sync(0xffffffffu, mx, o));

    float s = 0.f;
    #pragma unroll
    for (int t = 0; t < 16; ++t) { v[t] = __expf(v[t] - mx); s += v[t]; }
    #pragma unroll
    for (int o = 16; o; o >>= 1) s += __shfl_xor_sync(0xffffffffu, s, o);

    const float inv = __frcp_rn(s);
    __nv_bfloat162* oh = (__nv_bfloat162*)(g_ph + row * SEQ + lane * 16);
    __nv_bfloat162* ol = (__nv_bfloat162*)(g_pl + row * SEQ + lane * 16);
    #pragma unroll
    for (int c = 0; c < 8; ++c) {
        float a = v[2*c] * inv, b = v[2*c+1] * inv;
        __nv_bfloat16 ha = __float2bfloat16(a), hb = __float2bfloat16(b);
        __nv_bfloat16 la = __float2bfloat16(a - __bfloat162float(ha));
        __nv_bfloat16 lb = __float2bfloat16(b - __bfloat162float(hb));
        oh[c] = __nv_bfloat162(ha, hb);
        ol[c] = __nv_bfloat162(la, lb);
    }
}

// ===========================================================================
//  4) ctx = P @ V via 3-term MMA. grid (qt=4, bh=128). C tile 128x64.
//     warps 2(M) x 4(N): warp tile 64x16. K=512, BK=32, double buffered.
// ===========================================================================
#define PVE_P (128*PAD)        /* P tile elems  */
#define PVE_V (64*PAD)         /* V tile elems  */
#define PV_STAGE (2*PVE_P + 2*PVE_V)
#define PV_SMEM (2*PV_STAGE*2) /* bytes */

__global__ __launch_bounds__(256) void pv_mma()
{
    extern __shared__ __nv_bfloat16 smp[];
    const int bh = blockIdx.y, qt = blockIdx.x;
    const __nv_bfloat16* Ph = g_ph + ((size_t)bh * SEQ + qt * 128) * SEQ;
    const __nv_bfloat16* Pl = g_pl + ((size_t)bh * SEQ + qt * 128) * SEQ;
    const __nv_bfloat16* Vh = g_vh + (size_t)bh * HD * SEQ;
    const __nv_bfloat16* Vl = g_vl + (size_t)bh * HD * SEQ;

    const int tid = threadIdx.x;
    auto load_stage = [&](int kt, int s) {
        __nv_bfloat16* base = smp + (size_t)s * PV_STAGE;
        // P tiles: 128 rows x 32 cols, 2 chunks/thread each
        #pragma unroll
        for (int c = 0; c < 2; ++c) {
            int idx = tid + c * 256;
            int row = idx >> 2, chunk = idx & 3;
            cp_async16(smem_u32(base + row * PAD + chunk * 8),
                       Ph + (size_t)row * SEQ + kt * BK + chunk * 8);
            cp_async16(smem_u32(base + PVE_P + row * PAD + chunk * 8),
                       Pl + (size_t)row * SEQ + kt * BK + chunk * 8);
        }
        // V tiles: 64 rows x 32 cols, 1 chunk/thread each
        {
            int row = tid >> 2, chunk = tid & 3;
            cp_async16(smem_u32(base + 2 * PVE_P + row * PAD + chunk * 8),
                       Vh + (size_t)row * SEQ + kt * BK + chunk * 8);
            cp_async16(smem_u32(base + 2 * PVE_P + PVE_V + row * PAD + chunk * 8),
                       Vl + (size_t)row * SEQ + kt * BK + chunk * 8);
        }
    };

    const int warp = tid >> 5, lane = tid & 31;
    const int g = lane >> 2, t2 = (lane & 3) << 1;
    const int wm0 = (warp & 1) << 6;       // 0/64
    const int wn0 = (warp >> 1) << 4;      // 0,16,32,48
    float acc[4][2][4] = {};

    load_stage(0, 0);
    asm volatile("cp.async.commit_group;\n" ::: "memory");

    const int NKT2 = SEQ / BK;   // 16
    for (int kt = 0; kt < NKT2; ++kt) {
        const int cur = kt & 1;
        if (kt + 1 < NKT2) {
            load_stage(kt + 1, cur ^ 1);
            asm volatile("cp.async.commit_group;\n" ::: "memory");
            asm volatile("cp.async.wait_group 1;\n" ::: "memory");
        } else {
            asm volatile("cp.async.wait_group 0;\n" ::: "memory");
        }
        __syncthreads();

        const __nv_bfloat16* sPh = smp + (size_t)cur * PV_STAGE;
        const __nv_bfloat16* sPl = sPh + PVE_P;
        const __nv_bfloat16* sVh = sPh + 2 * PVE_P;
        const __nv_bfloat16* sVl = sVh + PVE_V;

        #pragma unroll
        for (int ks = 0; ks < BK; ks += 16) {
            uint32_t bhf[2][2], blf[2][2], a[4][4];
            #pragma unroll
            for (int j = 0; j < 2; ++j) {
                int r = (wn0 + j * 8 + g) * PAD + ks + t2;
                bhf[j][0] = ld2(sVh + r); bhf[j][1] = ld2(sVh + r + 8);
                blf[j][0] = ld2(sVl + r); blf[j][1] = ld2(sVl + r + 8);
            }
            #pragma unroll
            for (int i = 0; i < 4; ++i) {
                int r = (wm0 + i * 16 + g) * PAD + ks + t2;
                a[i][0] = ld2(sPh + r);     a[i][1] = ld2(sPh + r + 8 * PAD);
                a[i][2] = ld2(sPh + r + 8); a[i][3] = ld2(sPh + r + 8 * PAD + 8);
            }
            #pragma unroll
            for (int i = 0; i < 4; ++i)
                #pragma unroll
                for (int j = 0; j < 2; ++j) mma16(acc[i][j], a[i], bhf[j]);
            #pragma unroll
            for (int i = 0; i < 4; ++i)
                #pragma unroll
                for (int j = 0; j < 2; ++j) mma16(acc[i][j], a[i], blf[j]);
            #pragma unroll
            for (int i = 0; i < 4; ++i) {
                int r = (wm0 + i * 16 + g) * PAD + ks + t2;
                a[i][0] = ld2(sPl + r);     a[i][1] = ld2(sPl + r + 8 * PAD);
                a[i][2] = ld2(sPl + r + 8); a[i][3] = ld2(sPl + r + 8 * PAD + 8);
            }
            #pragma unroll
            for (int i = 0; i < 4; ++i)
                #pragma unroll
                for (int j = 0; j < 2; ++j) mma16(acc[i][j], a[i], bhf[j]);
        }
        __syncthreads();
    }

    const int b = bh >> 4, h = bh & 15;
    #pragma unroll
    for (int i = 0; i < 4; ++i)
        #pragma unroll
        for (int j = 0; j < 2; ++j)
            #pragma unroll
            for (int r = 0; r < 4; ++r) {
                int q = qt * 128 + wm0 + i * 16 + g + ((r >= 2) ? 8 : 0);
                int n = wn0 + j * 8 + t2 + (r & 1);
                size_t idx = ((size_t)(b * SEQ + q) * DIM) + h * HD + n;
                float v = acc[i][j][r];
                __nv_bfloat16 hh = __float2bfloat16(v);
                g_ch[idx] = hh;
                g_cl[idx] = __float2bfloat16(v - __bfloat162float(hh));
            }
}

// ---- 5) out projection + bias ---------------------------------------------
__global__ __launch_bounds__(256) void out_mma(const float* __restrict__ bo,
                                               float* __restrict__ out)
{
    extern __shared__ __nv_bfloat16 sm[];
    const __nv_bfloat16* Ah = g_ch + (size_t)blockIdx.y * 128 * DIM;
    const __nv_bfloat16* Al = g_cl + (size_t)blockIdx.y * 128 * DIM;
    const __nv_bfloat16* Bh = g_woh + (size_t)blockIdx.x * 128 * DIM;
    const __nv_bfloat16* Bl = g_wol + (size_t)blockIdx.x * 128 * DIM;

    float acc[4][4][4] = {};
    gemm3term(Ah, Al, Bh, Bl, sm, acc);

    const int warp = threadIdx.x >> 5, lane = threadIdx.x & 31;
    const int g = lane >> 2, t2 = (lane & 3) << 1;
    const int wm0 = (warp & 1) << 6, wn0 = (warp >> 1) << 5;
    #pragma unroll
    for (int i = 0; i < 4; ++i)
        #pragma unroll
        for (int j = 0; j < 4; ++j)
            #pragma unroll
            for (int r = 0; r < 4; ++r) {
                int m = blockIdx.y * 128 + wm0 + i * 16 + g + ((r >= 2) ? 8 : 0);
                int n = blockIdx.x * 128 + wn0 + j * 8 + t2 + (r & 1);
                out[(size_t)m * DIM + n] = acc[i][j][r] + bo[n];
            }
}

// ===========================================================================
extern "C" void kernel_launch(void* const* d_in, const int* in_sizes, int n_in,
                              void* d_out, int out_size)
{
    const float* x  = (const float*)d_in[0];
    const float* wq = (const float*)d_in[1];
    const float* wk = (const float*)d_in[2];
    const float* wv = (const float*)d_in[3];
    const float* wo = (const float*)d_in[4];
    const float* bo = (const float*)d_in[5];
    float* out = (float*)d_out;

    static bool attr_set = false;
    if (!attr_set) {
        cudaFuncSetAttribute(qkv_mma,    cudaFuncAttributeMaxDynamicSharedMemorySize, SMEM_BYTES);
        cudaFuncSetAttribute(out_mma,    cudaFuncAttributeMaxDynamicSharedMemorySize, SMEM_BYTES);
        cudaFuncSetAttribute(scores_mma, cudaFuncAttributeMaxDynamicSharedMemorySize, 4*TES*2);
        cudaFuncSetAttribute(pv_mma,     cudaFuncAttributeMaxDynamicSharedMemorySize, PV_SMEM);
        attr_set = true;
    }

    split_x<<<MROWS*DIM/4/256, 256>>>(x);
    split_w<<<dim3(DIM*DIM/4/256, 4), 256>>>(wq, wk, wv, wo);

    qkv_mma   <<<dim3(DIM/128, MROWS/128, 3), 256, SMEM_BYTES>>>();
    scores_mma<<<dim3(SEQ/128, SEQ/128, BH), 256, 4*TES*2>>>();
    softmax_kernel<<<(BH*SEQ)/8, 256>>>();
    pv_mma    <<<dim3(SEQ/128, BH), 256, PV_SMEM>>>();
    out_mma   <<<dim3(DIM/128, MROWS/128), 256, SMEM_BYTES>>>(bo, out);
}

// round 5
// speedup vs baseline: 2.6521x; 1.3614x over previous
#include <cuda_runtime.h>
#include <cuda_fp16.h>
#include <cstdint>

#define BATCH   8
#define SEQ     512
#define DIM     1024
#define HEADS   16
#define HD      64
#define NPATCH  196
#define MROWS   (BATCH*SEQ)     /* 4096 */
#define BH      (BATCH*HEADS)   /* 128  */

// ---------------- scratch (device globals: allocation-free) ----------------
__device__ float  g_sc [(size_t)BH*SEQ*SEQ];         // fp32 scores
__device__ __half g_xh [(size_t)MROWS*DIM];          // x split
__device__ __half g_xl [(size_t)MROWS*DIM];
__device__ __half g_wh [(size_t)3*DIM*DIM];          // wq,wk,wv hi only
__device__ __half g_woh[(size_t)DIM*DIM];            // wo hi only
__device__ __half g_qh [(size_t)BH*SEQ*HD];          // Q split [B,H,S,hd]
__device__ __half g_ql [(size_t)BH*SEQ*HD];
__device__ __half g_kh [(size_t)BH*SEQ*HD];          // K hi only
__device__ __half g_vh [(size_t)BH*HD*SEQ];          // V hi only, [B,H,hd,S]
__device__ __half g_ph [(size_t)BH*SEQ*SEQ];         // probs split
__device__ __half g_pl [(size_t)BH*SEQ*SEQ];
__device__ __half g_ch [(size_t)MROWS*DIM];          // ctx split [B,S,D]
__device__ __half g_cl [(size_t)MROWS*DIM];

__device__ __forceinline__ float neg_inf() { return __int_as_float(0xff800000); }

// ===========================================================================
//  split / convert kernels
// ===========================================================================
__global__ __launch_bounds__(256) void split_x(const float* __restrict__ x)
{
    size_t i = (size_t)blockIdx.x * 256 + threadIdx.x;   // float4 index
    float4 v = ((const float4*)x)[i];
    __half h0 = __float2half(v.x), h1 = __float2half(v.y);
    __half h2 = __float2half(v.z), h3 = __float2half(v.w);
    ((__half2*)g_xh)[i*2+0] = __halves2half2(h0, h1);
    ((__half2*)g_xh)[i*2+1] = __halves2half2(h2, h3);
    ((__half2*)g_xl)[i*2+0] = __halves2half2(__float2half(v.x - __half2float(h0)),
                                             __float2half(v.y - __half2float(h1)));
    ((__half2*)g_xl)[i*2+1] = __halves2half2(__float2half(v.z - __half2float(h2)),
                                             __float2half(v.w - __half2float(h3)));
}

__global__ __launch_bounds__(256) void split_w(const float* __restrict__ wq,
                                               const float* __restrict__ wk,
                                               const float* __restrict__ wv,
                                               const float* __restrict__ wo)
{
    int seg = blockIdx.y;
    const float* src = (seg == 0) ? wq : (seg == 1) ? wk : (seg == 2) ? wv : wo;
    __half* hi = (seg < 3) ? g_wh + (size_t)seg * DIM * DIM : g_woh;
    size_t i = (size_t)blockIdx.x * 256 + threadIdx.x;
    float4 v = ((const float4*)src)[i];
    ((__half2*)hi)[i*2+0] = __halves2half2(__float2half(v.x), __float2half(v.y));
    ((__half2*)hi)[i*2+1] = __halves2half2(__float2half(v.z), __float2half(v.w));
}

// ===========================================================================
//  common utils
// ===========================================================================
__device__ __forceinline__ uint32_t smem_u32(const void* p)
{ return (uint32_t)__cvta_generic_to_shared(p); }

__device__ __forceinline__ void cp_async16(uint32_t s, const void* g)
{ asm volatile("cp.async.cg.shared.global [%0], [%1], 16;\n" :: "r"(s), "l"(g)); }

__device__ __forceinline__ void ldsm4(uint32_t addr, uint32_t* r)
{
    asm volatile("ldmatrix.sync.aligned.m8n8.x4.shared.b16 {%0,%1,%2,%3}, [%4];"
                 : "=r"(r[0]), "=r"(r[1]), "=r"(r[2]), "=r"(r[3]) : "r"(addr));
}

__device__ __forceinline__ void mma16(float* c, const uint32_t* a, const uint32_t* b)
{
    asm volatile(
        "mma.sync.aligned.m16n8k16.row.col.f32.f16.f16.f32 "
        "{%0,%1,%2,%3},{%4,%5,%6,%7},{%8,%9},{%0,%1,%2,%3};"
        : "+f"(c[0]), "+f"(c[1]), "+f"(c[2]), "+f"(c[3])
        : "r"(a[0]), "r"(a[1]), "r"(a[2]), "r"(a[3]), "r"(b[0]), "r"(b[1]));
}

// ===========================================================================
//  2-term split-fp16 128x128xK GEMM (projections).  Tiles Ah|Al|Bh 128x32,
//  PAD=40 halves.  8 warps: 2(M)x4(N), warp tile 64x32.  ldmatrix frags.
// ===========================================================================
#define BK       32
#define PAD      40
#define TEH      (128*PAD)          /* halves per tile   */
#define STAGE_H  (3*TEH)            /* halves per stage  */
#define PRJ_SMEM (2*STAGE_H*2)      /* 61440 bytes       */
#define PRJ_NKT  (DIM/BK)           /* 32                */

__device__ __forceinline__ void gemm2(
    const __half* __restrict__ Ah, const __half* __restrict__ Al,
    const __half* __restrict__ Bh,
    __half* sm, float (&acc)[4][4][4])
{
    const int tid  = threadIdx.x;
    const int warp = tid >> 5, lane = tid & 31;
    const int wm0  = (warp & 1) << 6;
    const int wn0  = (warp >> 1) << 5;
    const int a_row = (lane & 7) + ((lane >> 3) & 1) * 8;
    const int a_k   = ((lane >> 4) & 1) * 8;
    const int b_row = (lane & 7) + ((lane >> 4) & 1) * 8;
    const int b_k   = ((lane >> 3) & 1) * 8;
    const uint32_t sb = smem_u32(sm);
    const __half* srcs[3] = {Ah, Al, Bh};

    auto load_stage = [&](int kt, int s) {
        uint32_t st = sb + (uint32_t)s * STAGE_H * 2;
        #pragma unroll
        for (int t = 0; t < 3; ++t) {
            uint32_t ob = st + (uint32_t)t * TEH * 2;
            #pragma unroll
            for (int c = 0; c < 2; ++c) {
                int idx = tid + c * 256;           // 0..511 chunks
                int row = idx >> 2, ch = idx & 3;
                cp_async16(ob + (uint32_t)(row * PAD + ch * 8) * 2,
                           srcs[t] + (size_t)row * DIM + kt * BK + ch * 8);
            }
        }
    };

    load_stage(0, 0);
    asm volatile("cp.async.commit_group;\n" ::: "memory");

    for (int kt = 0; kt < PRJ_NKT; ++kt) {
        const int cur = kt & 1;
        if (kt + 1 < PRJ_NKT) {
            load_stage(kt + 1, cur ^ 1);
            asm volatile("cp.async.commit_group;\n" ::: "memory");
            asm volatile("cp.async.wait_group 1;\n" ::: "memory");
        } else {
            asm volatile("cp.async.wait_group 0;\n" ::: "memory");
        }
        __syncthreads();

        const uint32_t st  = sb + (uint32_t)cur * STAGE_H * 2;
        const uint32_t sAh = st;
        const uint32_t sAl = st + TEH * 2;
        const uint32_t sBh = st + 2 * TEH * 2;

        #pragma unroll
        for (int ks = 0; ks < BK; ks += 16) {
            uint32_t b[4][2];
            #pragma unroll
            for (int jj = 0; jj < 2; ++jj) {
                uint32_t r[4];
                ldsm4(sBh + (uint32_t)((wn0 + jj*16 + b_row) * PAD + ks + b_k) * 2, r);
                b[jj*2+0][0] = r[0]; b[jj*2+0][1] = r[1];
                b[jj*2+1][0] = r[2]; b[jj*2+1][1] = r[3];
            }
            uint32_t af[4][4];
            #pragma unroll
            for (int i = 0; i < 4; ++i)
                ldsm4(sAh + (uint32_t)((wm0 + i*16 + a_row) * PAD + ks + a_k) * 2, af[i]);
            #pragma unroll
            for (int i = 0; i < 4; ++i)
                #pragma unroll
                for (int j = 0; j < 4; ++j) mma16(acc[i][j], af[i], b[j]);
            #pragma unroll
            for (int i = 0; i < 4; ++i)
                ldsm4(sAl + (uint32_t)((wm0 + i*16 + a_row) * PAD + ks + a_k) * 2, af[i]);
            #pragma unroll
            for (int i = 0; i < 4; ++i)
                #pragma unroll
                for (int j = 0; j < 4; ++j) mma16(acc[i][j], af[i], b[j]);
        }
        __syncthreads();
    }
}

// ---- 1) QKV projection: Q split, K hi, V hi transposed ---------------------
__global__ __launch_bounds__(256) void qkv_mma()
{
    extern __shared__ __half sm[];
    const int z = blockIdx.z;
    const __half* Ah = g_xh + (size_t)blockIdx.y * 128 * DIM;
    const __half* Al = g_xl + (size_t)blockIdx.y * 128 * DIM;
    const __half* Bh = g_wh + (size_t)z * DIM * DIM + (size_t)blockIdx.x * 128 * DIM;

    float acc[4][4][4] = {};
    gemm2(Ah, Al, Bh, sm, acc);

    const int warp = threadIdx.x >> 5, lane = threadIdx.x & 31;
    const int g = lane >> 2, t2 = (lane & 3) << 1;
    const int wm0 = (warp & 1) << 6, wn0 = (warp >> 1) << 5;
    #pragma unroll
    for (int i = 0; i < 4; ++i)
        #pragma unroll
        for (int j = 0; j < 4; ++j)
            #pragma unroll
            for (int r = 0; r < 4; ++r) {
                int m = blockIdx.y * 128 + wm0 + i * 16 + g + ((r >= 2) ? 8 : 0);
                int n = blockIdx.x * 128 + wn0 + j * 8 + t2 + (r & 1);
                int b = m >> 9, s = m & 511, h = n >> 6, d = n & 63;
                float v = acc[i][j][r];
                if (z == 0) {
                    size_t idx = ((size_t)(b * HEADS + h) * SEQ + s) * HD + d;
                    __half hh = __float2half(v);
                    g_qh[idx] = hh;
                    g_ql[idx] = __float2half(v - __half2float(hh));
                } else if (z == 1) {
                    size_t idx = ((size_t)(b * HEADS + h) * SEQ + s) * HD + d;
                    g_kh[idx] = __float2half(v);
                } else {
                    size_t idx = ((size_t)(b * HEADS + h) * HD + d) * SEQ + s;
                    g_vh[idx] = __float2half(v);
                }
            }
}

// ---- 5) out projection + bias ----------------------------------------------
__global__ __launch_bounds__(256) void out_mma(const float* __restrict__ bo,
                                               float* __restrict__ out)
{
    extern __shared__ __half sm[];
    const __half* Ah = g_ch + (size_t)blockIdx.y * 128 * DIM;
    const __half* Al = g_cl + (size_t)blockIdx.y * 128 * DIM;
    const __half* Bh = g_woh + (size_t)blockIdx.x * 128 * DIM;

    float acc[4][4][4] = {};
    gemm2(Ah, Al, Bh, sm, acc);

    const int warp = threadIdx.x >> 5, lane = threadIdx.x & 31;
    const int g = lane >> 2, t2 = (lane & 3) << 1;
    const int wm0 = (warp & 1) << 6, wn0 = (warp >> 1) << 5;
    #pragma unroll
    for (int i = 0; i < 4; ++i)
        #pragma unroll
        for (int j = 0; j < 4; ++j)
            #pragma unroll
            for (int r = 0; r < 4; ++r) {
                int m = blockIdx.y * 128 + wm0 + i * 16 + g + ((r >= 2) ? 8 : 0);
                int n = blockIdx.x * 128 + wn0 + j * 8 + t2 + (r & 1);
                out[(size_t)m * DIM + n] = acc[i][j][r] + bo[n];
            }
}

// ===========================================================================
//  2) scores = (Q K^T)/8, 2-term, mask fused, fully-masked tiles skipped.
//     Single K=64 stage.  Tiles Qh|Ql|Kh 128x64, PADS=72 halves.
// ===========================================================================
#define PADS 72
#define TESH (128*PADS)
#define SC_SMEM (3*TESH*2)

__global__ __launch_bounds__(256) void scores_mma()
{
    extern __shared__ __half sms[];
    const int bh = blockIdx.z;
    const int qt = blockIdx.y, kt = blockIdx.x;
    const int tid = threadIdx.x;

    if (kt > qt && !(qt == 0 && kt == 1)) {      // fully masked tile
        float4 m4 = make_float4(neg_inf(), neg_inf(), neg_inf(), neg_inf());
        float* outp = g_sc + (size_t)bh * SEQ * SEQ;
        #pragma unroll
        for (int t = 0; t < 16; ++t) {
            int idx = tid + t * 256;
            int row = idx >> 5, c4 = idx & 31;
            reinterpret_cast<float4*>(outp + (size_t)(qt*128 + row) * SEQ + kt*128)[c4] = m4;
        }
        return;
    }

    const __half* Qh = g_qh + ((size_t)bh * SEQ + qt * 128) * HD;
    const __half* Ql = g_ql + ((size_t)bh * SEQ + qt * 128) * HD;
    const __half* Kh = g_kh + ((size_t)bh * SEQ + kt * 128) * HD;
    const __half* srcs[3] = {Qh, Ql, Kh};
    #pragma unroll
    for (int t = 0; t < 3; ++t) {
        uint32_t dst = smem_u32(sms) + (uint32_t)t * TESH * 2;
        #pragma unroll
        for (int c = 0; c < 4; ++c) {
            int idx = tid + c * 256;               // 0..1023 chunks
            int row = idx >> 3, ch = idx & 7;
            cp_async16(dst + (uint32_t)(row * PADS + ch * 8) * 2,
                       srcs[t] + (size_t)row * HD + ch * 8);
        }
    }
    asm volatile("cp.async.commit_group;\n" ::: "memory");
    asm volatile("cp.async.wait_group 0;\n" ::: "memory");
    __syncthreads();

    const uint32_t sAh = smem_u32(sms);
    const uint32_t sAl = sAh + TESH * 2;
    const uint32_t sBh = sAh + 2 * TESH * 2;

    const int warp = tid >> 5, lane = tid & 31;
    const int g = lane >> 2, t2 = (lane & 3) << 1;
    const int wm0 = (warp & 1) << 6, wn0 = (warp >> 1) << 5;
    const int a_row = (lane & 7) + ((lane >> 3) & 1) * 8;
    const int a_k   = ((lane >> 4) & 1) * 8;
    const int b_row = (lane & 7) + ((lane >> 4) & 1) * 8;
    const int b_k   = ((lane >> 3) & 1) * 8;

    float acc[4][4][4] = {};
    #pragma unroll
    for (int ks = 0; ks < HD; ks += 16) {
        uint32_t b[4][2];
        #pragma unroll
        for (int jj = 0; jj < 2; ++jj) {
            uint32_t r[4];
            ldsm4(sBh + (uint32_t)((wn0 + jj*16 + b_row) * PADS + ks + b_k) * 2, r);
            b[jj*2+0][0] = r[0]; b[jj*2+0][1] = r[1];
            b[jj*2+1][0] = r[2]; b[jj*2+1][1] = r[3];
        }
        uint32_t af[4][4];
        #pragma unroll
        for (int i = 0; i < 4; ++i)
            ldsm4(sAh + (uint32_t)((wm0 + i*16 + a_row) * PADS + ks + a_k) * 2, af[i]);
        #pragma unroll
        for (int i = 0; i < 4; ++i)
            #pragma unroll
            for (int j = 0; j < 4; ++j) mma16(acc[i][j], af[i], b[j]);
        #pragma unroll
        for (int i = 0; i < 4; ++i)
            ldsm4(sAl + (uint32_t)((wm0 + i*16 + a_row) * PADS + ks + a_k) * 2, af[i]);
        #pragma unroll
        for (int i = 0; i < 4; ++i)
            #pragma unroll
            for (int j = 0; j < 4; ++j) mma16(acc[i][j], af[i], b[j]);
    }

    float* outp = g_sc + (size_t)bh * SEQ * SEQ;
    #pragma unroll
    for (int i = 0; i < 4; ++i)
        #pragma unroll
        for (int j = 0; j < 4; ++j)
            #pragma unroll
            for (int r = 0; r < 4; ++r) {
                int q = qt * 128 + wm0 + i * 16 + g + ((r >= 2) ? 8 : 0);
                int k = kt * 128 + wn0 + j * 8 + t2 + (r & 1);
                bool ok = (q < NPATCH) ? (k < NPATCH) : (k <= q);
                outp[(size_t)q * SEQ + k] = ok ? acc[i][j][r] * 0.125f : neg_inf();
            }
}

// ===========================================================================
//  3) row softmax -> split fp16 probs
// ===========================================================================
__global__ __launch_bounds__(256) void softmax_kernel()
{
    const int warp = threadIdx.x >> 5, lane = threadIdx.x & 31;
    const size_t row = (size_t)blockIdx.x * 8 + warp;
    const float* p = g_sc + row * SEQ + lane * 16;

    float v[16];
    float mx = neg_inf();
    #pragma unroll
    for (int c = 0; c < 4; ++c) {
        float4 lv = ((const float4*)p)[c];
        v[4*c+0] = lv.x; v[4*c+1] = lv.y; v[4*c+2] = lv.z; v[4*c+3] = lv.w;
    }
    #pragma unroll
    for (int t = 0; t < 16; ++t) mx = fmaxf(mx, v[t]);
    #pragma unroll
    for (int o = 16; o; o >>= 1) mx = fmaxf(mx, __shfl_xor_sync(0xffffffffu, mx, o));

    float s = 0.f;
    #pragma unroll
    for (int t = 0; t < 16; ++t) { v[t] = __expf(v[t] - mx); s += v[t]; }
    #pragma unroll
    for (int o = 16; o; o >>= 1) s += __shfl_xor_sync(0xffffffffu, s, o);

    const float inv = __frcp_rn(s);
    __half2* oh = (__half2*)(g_ph + row * SEQ + lane * 16);
    __half2* ol = (__half2*)(g_pl + row * SEQ + lane * 16);
    #pragma unroll
    for (int c = 0; c < 8; ++c) {
        float a = v[2*c] * inv, b = v[2*c+1] * inv;
        __half ha = __float2half(a), hb = __float2half(b);
        oh[c] = __halves2half2(ha, hb);
        ol[c] = __halves2half2(__float2half(a - __half2float(ha)),
                               __float2half(b - __half2float(hb)));
    }
}

// ===========================================================================
//  4) ctx = P @ V, 2-term, K trimmed per q-tile.  Tiles Ph|Pl 128x32, Vh 64x32.
//     8 warps: 2(M)x4(N), warp tile 64x16.
// ===========================================================================
#define PV_TP (128*PAD)                 /* P tile halves */
#define PV_TV (64*PAD)                  /* V tile halves */
#define PV_STAGE_H (2*PV_TP + PV_TV)
#define PV_SMEM (2*PV_STAGE_H*2)        /* 51200 bytes */

__global__ __launch_bounds__(256) void pv_mma()
{
    extern __shared__ __half smp[];
    const int bh = blockIdx.y, qt = blockIdx.x;
    const __half* Ph = g_ph + ((size_t)bh * SEQ + qt * 128) * SEQ;
    const __half* Pl = g_pl + ((size_t)bh * SEQ + qt * 128) * SEQ;
    const __half* Vh = g_vh + (size_t)bh * HD * SEQ;

    const int KEND[4] = {224, 256, 384, 512};
    const int NKT2 = KEND[qt] >> 5;

    const int tid = threadIdx.x;
    const uint32_t sb = smem_u32(smp);
    auto load_stage = [&](int kt, int s) {
        uint32_t st = sb + (uint32_t)s * PV_STAGE_H * 2;
        #pragma unroll
        for (int c = 0; c < 2; ++c) {
            int idx = tid + c * 256;
            int row = idx >> 2, ch = idx & 3;
            cp_async16(st + (uint32_t)(row * PAD + ch * 8) * 2,
                       Ph + (size_t)row * SEQ + kt * BK + ch * 8);
            cp_async16(st + (uint32_t)(PV_TP + row * PAD + ch * 8) * 2,
                       Pl + (size_t)row * SEQ + kt * BK + ch * 8);
        }
        {
            int row = tid >> 2, ch = tid & 3;
            cp_async16(st + (uint32_t)(2 * PV_TP + row * PAD + ch * 8) * 2,
                       Vh + (size_t)row * SEQ + kt * BK + ch * 8);
        }
    };

    const int warp = tid >> 5, lane = tid & 31;
    const int g = lane >> 2, t2 = (lane & 3) << 1;
    const int wm0 = (warp & 1) << 6;
    const int wn0 = (warp >> 1) << 4;
    const int a_row = (lane & 7) + ((lane >> 3) & 1) * 8;
    const int a_k   = ((lane >> 4) & 1) * 8;
    const int b_row = (lane & 7) + ((lane >> 4) & 1) * 8;
    const int b_k   = ((lane >> 3) & 1) * 8;
    float acc[4][2][4] = {};

    load_stage(0, 0);
    asm volatile("cp.async.commit_group;\n" ::: "memory");

    for (int kt = 0; kt < NKT2; ++kt) {
        const int cur = kt & 1;
        if (kt + 1 < NKT2) {
            load_stage(kt + 1, cur ^ 1);
            asm volatile("cp.async.commit_group;\n" ::: "memory");
            asm volatile("cp.async.wait_group 1;\n" ::: "memory");
        } else {
            asm volatile("cp.async.wait_group 0;\n" ::: "memory");
        }
        __syncthreads();

        const uint32_t st  = sb + (uint32_t)cur * PV_STAGE_H * 2;
        const uint32_t sPh = st;
        const uint32_t sPl = st + PV_TP * 2;
        const uint32_t sVh = st + 2 * PV_TP * 2;

        #pragma unroll
        for (int ks = 0; ks < BK; ks += 16) {
            uint32_t b[2][2];
            {
                uint32_t r[4];
                ldsm4(sVh + (uint32_t)((wn0 + b_row) * PAD + ks + b_k) * 2, r);
                b[0][0] = r[0]; b[0][1] = r[1];
                b[1][0] = r[2]; b[1][1] = r[3];
            }
            uint32_t af[4][4];
            #pragma unroll
            for (int i = 0; i < 4; ++i)
                ldsm4(sPh + (uint32_t)((wm0 + i*16 + a_row) * PAD + ks + a_k) * 2, af[i]);
            #pragma unroll
            for (int i = 0; i < 4; ++i)
                #pragma unroll
                for (int j = 0; j < 2; ++j) mma16(acc[i][j], af[i], b[j]);
            #pragma unroll
            for (int i = 0; i < 4; ++i)
                ldsm4(sPl + (uint32_t)((wm0 + i*16 + a_row) * PAD + ks + a_k) * 2, af[i]);
            #pragma unroll
            for (int i = 0; i < 4; ++i)
                #pragma unroll
                for (int j = 0; j < 2; ++j) mma16(acc[i][j], af[i], b[j]);
        }
        __syncthreads();
    }

    const int b = bh >> 4, h = bh & 15;
    #pragma unroll
    for (int i = 0; i < 4; ++i)
        #pragma unroll
        for (int j = 0; j < 2; ++j)
            #pragma unroll
            for (int r = 0; r < 4; ++r) {
                int q = qt * 128 + wm0 + i * 16 + g + ((r >= 2) ? 8 : 0);
                int n = wn0 + j * 8 + t2 + (r & 1);
                size_t idx = ((size_t)(b * SEQ + q) * DIM) + h * HD + n;
                float v = acc[i][j][r];
                __half hh = __float2half(v);
                g_ch[idx] = hh;
                g_cl[idx] = __float2half(v - __half2float(hh));
            }
}

// ===========================================================================
extern "C" void kernel_launch(void* const* d_in, const int* in_sizes, int n_in,
                              void* d_out, int out_size)
{
    const float* x  = (const float*)d_in[0];
    const float* wq = (const float*)d_in[1];
    const float* wk = (const float*)d_in[2];
    const float* wv = (const float*)d_in[3];
    const float* wo = (const float*)d_in[4];
    const float* bo = (const float*)d_in[5];
    float* out = (float*)d_out;

    static bool attr_set = false;
    if (!attr_set) {
        cudaFuncSetAttribute(qkv_mma,    cudaFuncAttributeMaxDynamicSharedMemorySize, PRJ_SMEM);
        cudaFuncSetAttribute(out_mma,    cudaFuncAttributeMaxDynamicSharedMemorySize, PRJ_SMEM);
        cudaFuncSetAttribute(scores_mma, cudaFuncAttributeMaxDynamicSharedMemorySize, SC_SMEM);
        cudaFuncSetAttribute(pv_mma,     cudaFuncAttributeMaxDynamicSharedMemorySize, PV_SMEM);
        attr_set = true;
    }

    split_x<<<MROWS*DIM/4/256, 256>>>(x);
    split_w<<<dim3(DIM*DIM/4/256, 4), 256>>>(wq, wk, wv, wo);

    qkv_mma   <<<dim3(DIM/128, MROWS/128, 3), 256, PRJ_SMEM>>>();
    scores_mma<<<dim3(SEQ/128, SEQ/128, BH), 256, SC_SMEM>>>();
    softmax_kernel<<<(BH*SEQ)/8, 256>>>();
    pv_mma    <<<dim3(SEQ/128, BH), 256, PV_SMEM>>>();
    out_mma   <<<dim3(DIM/128, MROWS/128), 256, PRJ_SMEM>>>(bo, out);
}

// round 6
// speedup vs baseline: 3.9809x; 1.5010x over previous
#include <cuda_runtime.h>
#include <cuda_fp16.h>
#include <cstdint>

#define BATCH   8
#define SEQ     512
#define DIM     1024
#define HEADS   16
#define HD      64
#define NPATCH  196
#define MROWS   (BATCH*SEQ)     /* 4096 */
#define BH      (BATCH*HEADS)   /* 128  */

// ---------------- scratch (device globals: allocation-free) ----------------
__device__ __half g_xh [(size_t)MROWS*DIM];          // x split
__device__ __half g_xl [(size_t)MROWS*DIM];
__device__ __half g_wh [(size_t)3*DIM*DIM];          // wq,wk,wv hi
__device__ __half g_woh[(size_t)DIM*DIM];            // wo hi
__device__ __half g_qh [(size_t)BH*SEQ*HD];          // Q split (pre-scaled by 1/8)
__device__ __half g_ql [(size_t)BH*SEQ*HD];
__device__ __half g_kh [(size_t)BH*SEQ*HD];          // K hi
__device__ __half g_vh [(size_t)BH*HD*SEQ];          // V hi, [B,H,hd,S]
__device__ __half g_ch [(size_t)MROWS*DIM];          // ctx split [B,S,D]
__device__ __half g_cl [(size_t)MROWS*DIM];

__device__ __forceinline__ float neg_inf() { return __int_as_float(0xff800000); }
__device__ __forceinline__ bool okqk(int q, int k)
{ return (q < NPATCH) ? (k < NPATCH) : (k <= q); }

// ===========================================================================
//  split / convert kernels
// ===========================================================================
__global__ __launch_bounds__(256) void split_x(const float* __restrict__ x)
{
    size_t i = (size_t)blockIdx.x * 256 + threadIdx.x;
    float4 v = ((const float4*)x)[i];
    __half h0 = __float2half(v.x), h1 = __float2half(v.y);
    __half h2 = __float2half(v.z), h3 = __float2half(v.w);
    ((__half2*)g_xh)[i*2+0] = __halves2half2(h0, h1);
    ((__half2*)g_xh)[i*2+1] = __halves2half2(h2, h3);
    ((__half2*)g_xl)[i*2+0] = __halves2half2(__float2half(v.x - __half2float(h0)),
                                             __float2half(v.y - __half2float(h1)));
    ((__half2*)g_xl)[i*2+1] = __halves2half2(__float2half(v.z - __half2float(h2)),
                                             __float2half(v.w - __half2float(h3)));
}

__global__ __launch_bounds__(256) void split_w(const float* __restrict__ wq,
                                               const float* __restrict__ wk,
                                               const float* __restrict__ wv,
                                               const float* __restrict__ wo)
{
    int seg = blockIdx.y;
    const float* src = (seg == 0) ? wq : (seg == 1) ? wk : (seg == 2) ? wv : wo;
    __half* hi = (seg < 3) ? g_wh + (size_t)seg * DIM * DIM : g_woh;
    size_t i = (size_t)blockIdx.x * 256 + threadIdx.x;
    float4 v = ((const float4*)src)[i];
    ((__half2*)hi)[i*2+0] = __halves2half2(__float2half(v.x), __float2half(v.y));
    ((__half2*)hi)[i*2+1] = __halves2half2(__float2half(v.z), __float2half(v.w));
}

// ===========================================================================
//  common utils
// ===========================================================================
__device__ __forceinline__ uint32_t smem_u32(const void* p)
{ return (uint32_t)__cvta_generic_to_shared(p); }

__device__ __forceinline__ void cp_async16(uint32_t s, const void* g)
{ asm volatile("cp.async.cg.shared.global [%0], [%1], 16;\n" :: "r"(s), "l"(g)); }

__device__ __forceinline__ void ldsm4(uint32_t addr, uint32_t* r)
{
    asm volatile("ldmatrix.sync.aligned.m8n8.x4.shared.b16 {%0,%1,%2,%3}, [%4];"
                 : "=r"(r[0]), "=r"(r[1]), "=r"(r[2]), "=r"(r[3]) : "r"(addr));
}

__device__ __forceinline__ void mma16(float* c, const uint32_t* a, const uint32_t* b)
{
    asm volatile(
        "mma.sync.aligned.m16n8k16.row.col.f32.f16.f16.f32 "
        "{%0,%1,%2,%3},{%4,%5,%6,%7},{%8,%9},{%0,%1,%2,%3};"
        : "+f"(c[0]), "+f"(c[1]), "+f"(c[2]), "+f"(c[3])
        : "r"(a[0]), "r"(a[1]), "r"(a[2]), "r"(a[3]), "r"(b[0]), "r"(b[1]));
}

// ===========================================================================
//  2-term split-fp16 128x128xK GEMM (projections). 3-stage cp.async pipeline.
// ===========================================================================
#define BK       32
#define PAD      40
#define TEH      (128*PAD)
#define STAGE_H  (3*TEH)
#define PRJ_SMEM (3*STAGE_H*2)      /* 92160 bytes */
#define PRJ_NKT  (DIM/BK)           /* 32 */

__device__ __forceinline__ void gemm2(
    const __half* __restrict__ Ah, const __half* __restrict__ Al,
    const __half* __restrict__ Bh,
    __half* sm, float (&acc)[4][4][4])
{
    const int tid  = threadIdx.x;
    const int warp = tid >> 5, lane = tid & 31;
    const int wm0  = (warp & 1) << 6;
    const int wn0  = (warp >> 1) << 5;
    const int a_row = (lane & 7) + ((lane >> 3) & 1) * 8;
    const int a_k   = ((lane >> 4) & 1) * 8;
    const int b_row = (lane & 7) + ((lane >> 4) & 1) * 8;
    const int b_k   = ((lane >> 3) & 1) * 8;
    const uint32_t sb = smem_u32(sm);
    const __half* srcs[3] = {Ah, Al, Bh};

    auto load_stage = [&](int kt, int s) {
        uint32_t st = sb + (uint32_t)s * STAGE_H * 2;
        #pragma unroll
        for (int t = 0; t < 3; ++t) {
            uint32_t ob = st + (uint32_t)t * TEH * 2;
            #pragma unroll
            for (int c = 0; c < 2; ++c) {
                int idx = tid + c * 256;
                int row = idx >> 2, ch = idx & 3;
                cp_async16(ob + (uint32_t)(row * PAD + ch * 8) * 2,
                           srcs[t] + (size_t)row * DIM + kt * BK + ch * 8);
            }
        }
    };

    load_stage(0, 0);
    asm volatile("cp.async.commit_group;\n" ::: "memory");
    load_stage(1, 1);
    asm volatile("cp.async.commit_group;\n" ::: "memory");

    for (int kt = 0; kt < PRJ_NKT; ++kt) {
        const int cur = kt % 3;
        if (kt + 2 < PRJ_NKT) {
            load_stage(kt + 2, (kt + 2) % 3);
            asm volatile("cp.async.commit_group;\n" ::: "memory");
            asm volatile("cp.async.wait_group 2;\n" ::: "memory");
        } else if (kt + 1 < PRJ_NKT) {
            asm volatile("cp.async.wait_group 1;\n" ::: "memory");
        } else {
            asm volatile("cp.async.wait_group 0;\n" ::: "memory");
        }
        __syncthreads();

        const uint32_t st  = sb + (uint32_t)cur * STAGE_H * 2;
        const uint32_t sAh = st;
        const uint32_t sAl = st + TEH * 2;
        const uint32_t sBh = st + 2 * TEH * 2;

        #pragma unroll
        for (int ks = 0; ks < BK; ks += 16) {
            uint32_t b[4][2];
            #pragma unroll
            for (int jj = 0; jj < 2; ++jj) {
                uint32_t r[4];
                ldsm4(sBh + (uint32_t)((wn0 + jj*16 + b_row) * PAD + ks + b_k) * 2, r);
                b[jj*2+0][0] = r[0]; b[jj*2+0][1] = r[1];
                b[jj*2+1][0] = r[2]; b[jj*2+1][1] = r[3];
            }
            uint32_t af[4][4];
            #pragma unroll
            for (int i = 0; i < 4; ++i)
                ldsm4(sAh + (uint32_t)((wm0 + i*16 + a_row) * PAD + ks + a_k) * 2, af[i]);
            #pragma unroll
            for (int i = 0; i < 4; ++i)
                #pragma unroll
                for (int j = 0; j < 4; ++j) mma16(acc[i][j], af[i], b[j]);
            #pragma unroll
            for (int i = 0; i < 4; ++i)
                ldsm4(sAl + (uint32_t)((wm0 + i*16 + a_row) * PAD + ks + a_k) * 2, af[i]);
            #pragma unroll
            for (int i = 0; i < 4; ++i)
                #pragma unroll
                for (int j = 0; j < 4; ++j) mma16(acc[i][j], af[i], b[j]);
        }
        __syncthreads();
    }
}

// ---- 1) QKV projection: Q split (scaled by 1/8), K hi, V hi transposed -----
__global__ __launch_bounds__(256) void qkv_mma()
{
    extern __shared__ __half sm[];
    const int z = blockIdx.z;
    const __half* Ah = g_xh + (size_t)blockIdx.y * 128 * DIM;
    const __half* Al = g_xl + (size_t)blockIdx.y * 128 * DIM;
    const __half* Bh = g_wh + (size_t)z * DIM * DIM + (size_t)blockIdx.x * 128 * DIM;

    float acc[4][4][4] = {};
    gemm2(Ah, Al, Bh, sm, acc);

    const int warp = threadIdx.x >> 5, lane = threadIdx.x & 31;
    const int g = lane >> 2, t2 = (lane & 3) << 1;
    const int wm0 = (warp & 1) << 6, wn0 = (warp >> 1) << 5;
    #pragma unroll
    for (int i = 0; i < 4; ++i)
        #pragma unroll
        for (int j = 0; j < 4; ++j)
            #pragma unroll
            for (int r = 0; r < 4; ++r) {
                int m = blockIdx.y * 128 + wm0 + i * 16 + g + ((r >= 2) ? 8 : 0);
                int n = blockIdx.x * 128 + wn0 + j * 8 + t2 + (r & 1);
                int b = m >> 9, s = m & 511, h = n >> 6, d = n & 63;
                float v = acc[i][j][r];
                if (z == 0) {
                    v *= 0.125f;                       // fold 1/sqrt(hd)
                    size_t idx = ((size_t)(b * HEADS + h) * SEQ + s) * HD + d;
                    __half hh = __float2half(v);
                    g_qh[idx] = hh;
                    g_ql[idx] = __float2half(v - __half2float(hh));
                } else if (z == 1) {
                    size_t idx = ((size_t)(b * HEADS + h) * SEQ + s) * HD + d;
                    g_kh[idx] = __float2half(v);
                } else {
                    size_t idx = ((size_t)(b * HEADS + h) * HD + d) * SEQ + s;
                    g_vh[idx] = __float2half(v);
                }
            }
}

// ---- 5) out projection + bias ----------------------------------------------
__global__ __launch_bounds__(256) void out_mma(const float* __restrict__ bo,
                                               float* __restrict__ out)
{
    extern __shared__ __half sm[];
    const __half* Ah = g_ch + (size_t)blockIdx.y * 128 * DIM;
    const __half* Al = g_cl + (size_t)blockIdx.y * 128 * DIM;
    const __half* Bh = g_woh + (size_t)blockIdx.x * 128 * DIM;

    float acc[4][4][4] = {};
    gemm2(Ah, Al, Bh, sm, acc);

    const int warp = threadIdx.x >> 5, lane = threadIdx.x & 31;
    const int g = lane >> 2, t2 = (lane & 3) << 1;
    const int wm0 = (warp & 1) << 6, wn0 = (warp >> 1) << 5;
    #pragma unroll
    for (int i = 0; i < 4; ++i)
        #pragma unroll
        for (int j = 0; j < 4; ++j)
            #pragma unroll
            for (int r = 0; r < 4; ++r) {
                int m = blockIdx.y * 128 + wm0 + i * 16 + g + ((r >= 2) ? 8 : 0);
                int n = blockIdx.x * 128 + wn0 + j * 8 + t2 + (r & 1);
                out[(size_t)m * DIM + n] = acc[i][j][r] + bo[n];
            }
}

// ===========================================================================
//  fused flash attention: per (qt, bh) CTA, 8 warps x 16 query rows.
// ===========================================================================
#define FA_PADK 72
#define FA_PADV 136
#define FA_KH   (128*FA_PADK)            /* halves */
#define FA_VT   (64*FA_PADV)
#define FA_STAGE_H (FA_KH + FA_VT)
#define FA_Q_H  (2*128*FA_PADK)
#define FA_SMEM ((FA_Q_H + 2*FA_STAGE_H)*2)   /* 108544 B */

__global__ __launch_bounds__(256) void flash_attn()
{
    extern __shared__ __half fsm[];
    const int qt = blockIdx.x, bh = blockIdx.y;
    const int tid = threadIdx.x, warp = tid >> 5, lane = tid & 31;
    const int g = lane >> 2, t2 = (lane & 3) << 1;
    const int a_row = (lane & 7) + ((lane >> 3) & 1) * 8;
    const int a_k   = ((lane >> 4) & 1) * 8;
    const int b_row = (lane & 7) + ((lane >> 4) & 1) * 8;
    const int b_k   = ((lane >> 3) & 1) * 8;

    const int NT[4] = {2, 2, 3, 4};
    const int ntiles = NT[qt];

    const __half* Qh = g_qh + ((size_t)bh * SEQ + qt * 128) * HD;
    const __half* Ql = g_ql + ((size_t)bh * SEQ + qt * 128) * HD;
    const __half* Kh = g_kh + (size_t)bh * SEQ * HD;
    const __half* Vt = g_vh + (size_t)bh * HD * SEQ;

    const uint32_t sb  = smem_u32(fsm);
    const uint32_t sQh = sb;
    const uint32_t sQl = sb + (uint32_t)128 * FA_PADK * 2;
    const uint32_t sStg = sb + (uint32_t)FA_Q_H * 2;

    #pragma unroll
    for (int c = 0; c < 4; ++c) {
        int idx = tid + c * 256;
        int row = idx >> 3, ch = idx & 7;
        cp_async16(sQh + (uint32_t)(row * FA_PADK + ch * 8) * 2, Qh + (size_t)row * HD + ch * 8);
        cp_async16(sQl + (uint32_t)(row * FA_PADK + ch * 8) * 2, Ql + (size_t)row * HD + ch * 8);
    }
    asm volatile("cp.async.commit_group;\n" ::: "memory");

    auto load_kv = [&](int t, int s) {
        uint32_t st = sStg + (uint32_t)s * FA_STAGE_H * 2;
        #pragma unroll
        for (int c = 0; c < 4; ++c) {
            int idx = tid + c * 256;
            int row = idx >> 3, ch = idx & 7;
            cp_async16(st + (uint32_t)(row * FA_PADK + ch * 8) * 2,
                       Kh + (size_t)(t * 128 + row) * HD + ch * 8);
        }
        uint32_t sv = st + (uint32_t)FA_KH * 2;
        #pragma unroll
        for (int c = 0; c < 4; ++c) {
            int idx = tid + c * 256;
            int row = idx >> 4, ch = idx & 15;
            cp_async16(sv + (uint32_t)(row * FA_PADV + ch * 8) * 2,
                       Vt + (size_t)row * SEQ + t * 128 + ch * 8);
        }
    };

    load_kv(0, 0);
    asm volatile("cp.async.commit_group;\n" ::: "memory");

    asm volatile("cp.async.wait_group 1;\n" ::: "memory");
    __syncthreads();
    uint32_t qfh[4][4], qfl[4][4];
    #pragma unroll
    for (int ks = 0; ks < 4; ++ks) {
        ldsm4(sQh + (uint32_t)((warp * 16 + a_row) * FA_PADK + ks * 16 + a_k) * 2, qfh[ks]);
        ldsm4(sQl + (uint32_t)((warp * 16 + a_row) * FA_PADK + ks * 16 + a_k) * 2, qfl[ks]);
    }

    float acc_o[8][4] = {};
    float m0 = neg_inf(), m1 = neg_inf(), l0 = 0.f, l1 = 0.f;

    for (int t = 0; t < ntiles; ++t) {
        if (t + 1 < ntiles) {
            load_kv(t + 1, (t + 1) & 1);
            asm volatile("cp.async.commit_group;\n" ::: "memory");
            asm volatile("cp.async.wait_group 1;\n" ::: "memory");
        } else {
            asm volatile("cp.async.wait_group 0;\n" ::: "memory");
        }
        __syncthreads();

        const uint32_t st = sStg + (uint32_t)(t & 1) * FA_STAGE_H * 2;
        const uint32_t sK = st;
        const uint32_t sV = st + (uint32_t)FA_KH * 2;

        // ---- S = Q K^T (2-term), warp tile 16x128 ----
        float s[16][4];
        #pragma unroll
        for (int j = 0; j < 16; ++j)
            #pragma unroll
            for (int r = 0; r < 4; ++r) s[j][r] = 0.f;

        #pragma unroll
        for (int ks = 0; ks < 4; ++ks) {
            uint32_t bfr[16][2];
            #pragma unroll
            for (int jj = 0; jj < 8; ++jj) {
                uint32_t r[4];
                ldsm4(sK + (uint32_t)((jj*16 + b_row) * FA_PADK + ks*16 + b_k) * 2, r);
                bfr[jj*2+0][0] = r[0]; bfr[jj*2+0][1] = r[1];
                bfr[jj*2+1][0] = r[2]; bfr[jj*2+1][1] = r[3];
            }
            #pragma unroll
            for (int j = 0; j < 16; ++j) {
                mma16(s[j], qfh[ks], bfr[j]);
                mma16(s[j], qfl[ks], bfr[j]);
            }
        }

        if (t == ntiles - 1) {
            const int q0 = qt * 128 + warp * 16 + g, q1 = q0 + 8;
            #pragma unroll
            for (int j = 0; j < 16; ++j) {
                int k0 = t * 128 + j * 8 + t2;
                if (!okqk(q0, k0))     s[j][0] = neg_inf();
                if (!okqk(q0, k0 + 1)) s[j][1] = neg_inf();
                if (!okqk(q1, k0))     s[j][2] = neg_inf();
                if (!okqk(q1, k0 + 1)) s[j][3] = neg_inf();
            }
        }

        // ---- online softmax ----
        float mx0 = neg_inf(), mx1 = neg_inf();
        #pragma unroll
        for (int j = 0; j < 16; ++j) {
            mx0 = fmaxf(mx0, fmaxf(s[j][0], s[j][1]));
            mx1 = fmaxf(mx1, fmaxf(s[j][2], s[j][3]));
        }
        mx0 = fmaxf(mx0, __shfl_xor_sync(0xffffffffu, mx0, 1));
        mx0 = fmaxf(mx0, __shfl_xor_sync(0xffffffffu, mx0, 2));
        mx1 = fmaxf(mx1, __shfl_xor_sync(0xffffffffu, mx1, 1));
        mx1 = fmaxf(mx1, __shfl_xor_sync(0xffffffffu, mx1, 2));

        const float mn0 = fmaxf(m0, mx0), mn1 = fmaxf(m1, mx1);
        const float sc0 = __expf(m0 - mn0), sc1 = __expf(m1 - mn1);
        m0 = mn0; m1 = mn1;

        float sum0 = 0.f, sum1 = 0.f;
        #pragma unroll
        for (int j = 0; j < 16; ++j) {
            s[j][0] = __expf(s[j][0] - mn0); sum0 += s[j][0];
            s[j][1] = __expf(s[j][1] - mn0); sum0 += s[j][1];
            s[j][2] = __expf(s[j][2] - mn1); sum1 += s[j][2];
            s[j][3] = __expf(s[j][3] - mn1); sum1 += s[j][3];
        }
        sum0 += __shfl_xor_sync(0xffffffffu, sum0, 1);
        sum0 += __shfl_xor_sync(0xffffffffu, sum0, 2);
        sum1 += __shfl_xor_sync(0xffffffffu, sum1, 1);
        sum1 += __shfl_xor_sync(0xffffffffu, sum1, 2);
        l0 = l0 * sc0 + sum0;
        l1 = l1 * sc1 + sum1;

        #pragma unroll
        for (int jn = 0; jn < 8; ++jn) {
            acc_o[jn][0] *= sc0; acc_o[jn][1] *= sc0;
            acc_o[jn][2] *= sc1; acc_o[jn][3] *= sc1;
        }

        // ---- O += P V (P split hi/lo, in-register repack) ----
        #pragma unroll
        for (int ks = 0; ks < 8; ++ks) {
            uint32_t bv[8][2];
            #pragma unroll
            for (int jj = 0; jj < 4; ++jj) {
                uint32_t r[4];
                ldsm4(sV + (uint32_t)((jj*16 + b_row) * FA_PADV + ks*16 + b_k) * 2, r);
                bv[jj*2+0][0] = r[0]; bv[jj*2+0][1] = r[1];
                bv[jj*2+1][0] = r[2]; bv[jj*2+1][1] = r[3];
            }
            uint32_t pah[4], pal[4];
            #pragma unroll
            for (int half = 0; half < 2; ++half) {
                const float* ps = s[2*ks + half];
                __half h0 = __float2half(ps[0]), h1 = __float2half(ps[1]);
                __half h2 = __float2half(ps[2]), h3 = __float2half(ps[3]);
                __half2 ah = __halves2half2(h0, h1);
                __half2 bhv = __halves2half2(h2, h3);
                __half2 al = __halves2half2(__float2half(ps[0] - __half2float(h0)),
                                            __float2half(ps[1] - __half2float(h1)));
                __half2 bl = __halves2half2(__float2half(ps[2] - __half2float(h2)),
                                            __float2half(ps[3] - __half2float(h3)));
                pah[half*2+0] = *reinterpret_cast<uint32_t*>(&ah);
                pah[half*2+1] = *reinterpret_cast<uint32_t*>(&bhv);
                pal[half*2+0] = *reinterpret_cast<uint32_t*>(&al);
                pal[half*2+1] = *reinterpret_cast<uint32_t*>(&bl);
            }
            // reorder: frag = {rowg klo, rowg+8 klo, rowg khi, rowg+8 khi}
            uint32_t tmp;
            tmp = pah[1]; pah[1] = pah[1]; // no-op placeholder removed below
            // Correct mapping: half=0 gave {a0=row g k t2, a1=row g+8 k t2} -> pah[0],pah[1]
            //                  half=1 gave {a2=row g k t2+8, a3=row g+8 k t2+8} -> pah[2],pah[3]
            (void)tmp;
            #pragma unroll
            for (int jn = 0; jn < 8; ++jn) {
                mma16(acc_o[jn], pah, bv[jn]);
                mma16(acc_o[jn], pal, bv[jn]);
            }
        }
        __syncthreads();
    }

    const float il0 = __frcp_rn(l0), il1 = __frcp_rn(l1);
    const int b = bh >> 4, h = bh & 15;
    const int q0 = qt * 128 + warp * 16 + g;
    #pragma unroll
    for (int jn = 0; jn < 8; ++jn)
        #pragma unroll
        for (int r = 0; r < 4; ++r) {
            int q = (r >= 2) ? q0 + 8 : q0;
            float v = acc_o[jn][r] * ((r >= 2) ? il1 : il0);
            int n = jn * 8 + t2 + (r & 1);
            size_t idx = ((size_t)(b * SEQ + q) * DIM) + h * HD + n;
            __half hh = __float2half(v);
            g_ch[idx] = hh;
            g_cl[idx] = __float2half(v - __half2float(hh));
        }
}

// ===========================================================================
extern "C" void kernel_launch(void* const* d_in, const int* in_sizes, int n_in,
                              void* d_out, int out_size)
{
    const float* x  = (const float*)d_in[0];
    const float* wq = (const float*)d_in[1];
    const float* wk = (const float*)d_in[2];
    const float* wv = (const float*)d_in[3];
    const float* wo = (const float*)d_in[4];
    const float* bo = (const float*)d_in[5];
    float* out = (float*)d_out;

    static bool attr_set = false;
    if (!attr_set) {
        cudaFuncSetAttribute(qkv_mma,    cudaFuncAttributeMaxDynamicSharedMemorySize, PRJ_SMEM);
        cudaFuncSetAttribute(out_mma,    cudaFuncAttributeMaxDynamicSharedMemorySize, PRJ_SMEM);
        cudaFuncSetAttribute(flash_attn, cudaFuncAttributeMaxDynamicSharedMemorySize, FA_SMEM);
        attr_set = true;
    }

    split_x<<<MROWS*DIM/4/256, 256>>>(x);
    split_w<<<dim3(DIM*DIM/4/256, 4), 256>>>(wq, wk, wv, wo);

    qkv_mma   <<<dim3(DIM/128, MROWS/128, 3), 256, PRJ_SMEM>>>();
    flash_attn<<<dim3(SEQ/128, BH), 256, FA_SMEM>>>();
    out_mma   <<<dim3(DIM/128, MROWS/128), 256, PRJ_SMEM>>>(bo, out);
}

// round 7
// speedup vs baseline: 4.0776x; 1.0243x over previous
#include <cuda_runtime.h>
#include <cuda_fp16.h>
#include <cstdint>

#define BATCH   8
#define SEQ     512
#define DIM     1024
#define HEADS   16
#define HD      64
#define NPATCH  196
#define MROWS   (BATCH*SEQ)     /* 4096 */
#define BH      (BATCH*HEADS)   /* 128  */

// ---------------- scratch (device globals: allocation-free) ----------------
__device__ __half g_xh [(size_t)MROWS*DIM];          // x split
__device__ __half g_xl [(size_t)MROWS*DIM];
__device__ __half g_wh [(size_t)3*DIM*DIM];          // wq,wk,wv hi
__device__ __half g_woh[(size_t)DIM*DIM];            // wo hi
__device__ __half g_qh [(size_t)BH*SEQ*HD];          // Q split (pre-scaled by 1/8)
__device__ __half g_ql [(size_t)BH*SEQ*HD];
__device__ __half g_kh [(size_t)BH*SEQ*HD];          // K hi
__device__ __half g_vh [(size_t)BH*HD*SEQ];          // V hi, [B,H,hd,S]
__device__ __half g_ch [(size_t)MROWS*DIM];          // ctx split [B,S,D]
__device__ __half g_cl [(size_t)MROWS*DIM];

__device__ __forceinline__ float neg_inf() { return __int_as_float(0xff800000); }
__device__ __forceinline__ bool okqk(int q, int k)
{ return (q < NPATCH) ? (k < NPATCH) : (k <= q); }

// ===========================================================================
//  split / convert kernels
// ===========================================================================
__global__ __launch_bounds__(256) void split_x(const float* __restrict__ x)
{
    size_t i = (size_t)blockIdx.x * 256 + threadIdx.x;
    float4 v = ((const float4*)x)[i];
    __half h0 = __float2half(v.x), h1 = __float2half(v.y);
    __half h2 = __float2half(v.z), h3 = __float2half(v.w);
    ((__half2*)g_xh)[i*2+0] = __halves2half2(h0, h1);
    ((__half2*)g_xh)[i*2+1] = __halves2half2(h2, h3);
    ((__half2*)g_xl)[i*2+0] = __halves2half2(__float2half(v.x - __half2float(h0)),
                                             __float2half(v.y - __half2float(h1)));
    ((__half2*)g_xl)[i*2+1] = __halves2half2(__float2half(v.z - __half2float(h2)),
                                             __float2half(v.w - __half2float(h3)));
}

__global__ __launch_bounds__(256) void split_w(const float* __restrict__ wq,
                                               const float* __restrict__ wk,
                                               const float* __restrict__ wv,
                                               const float* __restrict__ wo)
{
    int seg = blockIdx.y;
    const float* src = (seg == 0) ? wq : (seg == 1) ? wk : (seg == 2) ? wv : wo;
    __half* hi = (seg < 3) ? g_wh + (size_t)seg * DIM * DIM : g_woh;
    size_t i = (size_t)blockIdx.x * 256 + threadIdx.x;
    float4 v = ((const float4*)src)[i];
    ((__half2*)hi)[i*2+0] = __halves2half2(__float2half(v.x), __float2half(v.y));
    ((__half2*)hi)[i*2+1] = __halves2half2(__float2half(v.z), __float2half(v.w));
}

// ===========================================================================
//  common utils
// ===========================================================================
__device__ __forceinline__ uint32_t smem_u32(const void* p)
{ return (uint32_t)__cvta_generic_to_shared(p); }

__device__ __forceinline__ void cp_async16(uint32_t s, const void* g)
{ asm volatile("cp.async.cg.shared.global [%0], [%1], 16;\n" :: "r"(s), "l"(g)); }

__device__ __forceinline__ void ldsm4(uint32_t addr, uint32_t* r)
{
    asm volatile("ldmatrix.sync.aligned.m8n8.x4.shared.b16 {%0,%1,%2,%3}, [%4];"
                 : "=r"(r[0]), "=r"(r[1]), "=r"(r[2]), "=r"(r[3]) : "r"(addr));
}

__device__ __forceinline__ void mma16(float* c, const uint32_t* a, const uint32_t* b)
{
    asm volatile(
        "mma.sync.aligned.m16n8k16.row.col.f32.f16.f16.f32 "
        "{%0,%1,%2,%3},{%4,%5,%6,%7},{%8,%9},{%0,%1,%2,%3};"
        : "+f"(c[0]), "+f"(c[1]), "+f"(c[2]), "+f"(c[3])
        : "r"(a[0]), "r"(a[1]), "r"(a[2]), "r"(a[3]), "r"(b[0]), "r"(b[1]));
}

// ===========================================================================
//  2-term split-fp16 128x256xK GEMM (projections). 3-stage cp.async pipeline.
//  8 warps 2(M)x4(N), warp tile 64x64.
// ===========================================================================
#define BK       32
#define PAD      40
#define A_TEH    (128*PAD)          /* halves per A tile  */
#define B_TEH    (256*PAD)          /* halves per B tile  */
#define STAGE_H  (2*A_TEH + B_TEH)  /* 20480 halves       */
#define PRJ_SMEM (3*STAGE_H*2)      /* 122880 bytes       */
#define PRJ_NKT  (DIM/BK)           /* 32                 */

__device__ __forceinline__ void gemm2(
    const __half* __restrict__ Ah, const __half* __restrict__ Al,
    const __half* __restrict__ Bh,
    __half* sm, float (&acc)[4][8][4])
{
    const int tid  = threadIdx.x;
    const int warp = tid >> 5, lane = tid & 31;
    const int wm0  = (warp & 1) << 6;       // 0/64
    const int wn0  = (warp >> 1) << 6;      // 0,64,128,192
    const int a_row = (lane & 7) + ((lane >> 3) & 1) * 8;
    const int a_k   = ((lane >> 4) & 1) * 8;
    const int b_row = (lane & 7) + ((lane >> 4) & 1) * 8;
    const int b_k   = ((lane >> 3) & 1) * 8;
    const uint32_t sb = smem_u32(sm);

    auto load_stage = [&](int kt, int s) {
        uint32_t st = sb + (uint32_t)s * STAGE_H * 2;
        // Ah, Al: 128 rows x 4 chunks = 512 chunks each
        #pragma unroll
        for (int c = 0; c < 2; ++c) {
            int idx = tid + c * 256;
            int row = idx >> 2, ch = idx & 3;
            cp_async16(st + (uint32_t)(row * PAD + ch * 8) * 2,
                       Ah + (size_t)row * DIM + kt * BK + ch * 8);
            cp_async16(st + (uint32_t)(A_TEH + row * PAD + ch * 8) * 2,
                       Al + (size_t)row * DIM + kt * BK + ch * 8);
        }
        // Bh: 256 rows x 4 chunks = 1024 chunks
        uint32_t bb = st + (uint32_t)(2 * A_TEH) * 2;
        #pragma unroll
        for (int c = 0; c < 4; ++c) {
            int idx = tid + c * 256;
            int row = idx >> 2, ch = idx & 3;
            cp_async16(bb + (uint32_t)(row * PAD + ch * 8) * 2,
                       Bh + (size_t)row * DIM + kt * BK + ch * 8);
        }
    };

    load_stage(0, 0);
    asm volatile("cp.async.commit_group;\n" ::: "memory");
    load_stage(1, 1);
    asm volatile("cp.async.commit_group;\n" ::: "memory");

    for (int kt = 0; kt < PRJ_NKT; ++kt) {
        const int cur = kt % 3;
        if (kt + 2 < PRJ_NKT) {
            load_stage(kt + 2, (kt + 2) % 3);
            asm volatile("cp.async.commit_group;\n" ::: "memory");
            asm volatile("cp.async.wait_group 2;\n" ::: "memory");
        } else if (kt + 1 < PRJ_NKT) {
            asm volatile("cp.async.wait_group 1;\n" ::: "memory");
        } else {
            asm volatile("cp.async.wait_group 0;\n" ::: "memory");
        }
        __syncthreads();

        const uint32_t st  = sb + (uint32_t)cur * STAGE_H * 2;
        const uint32_t sAh = st;
        const uint32_t sAl = st + A_TEH * 2;
        const uint32_t sBh = st + 2 * A_TEH * 2;

        #pragma unroll
        for (int ks = 0; ks < BK; ks += 16) {
            uint32_t b[8][2];
            #pragma unroll
            for (int jj = 0; jj < 4; ++jj) {
                uint32_t r[4];
                ldsm4(sBh + (uint32_t)((wn0 + jj*16 + b_row) * PAD + ks + b_k) * 2, r);
                b[jj*2+0][0] = r[0]; b[jj*2+0][1] = r[1];
                b[jj*2+1][0] = r[2]; b[jj*2+1][1] = r[3];
            }
            uint32_t af[4][4];
            #pragma unroll
            for (int i = 0; i < 4; ++i)
                ldsm4(sAh + (uint32_t)((wm0 + i*16 + a_row) * PAD + ks + a_k) * 2, af[i]);
            #pragma unroll
            for (int i = 0; i < 4; ++i)
                #pragma unroll
                for (int j = 0; j < 8; ++j) mma16(acc[i][j], af[i], b[j]);
            #pragma unroll
            for (int i = 0; i < 4; ++i)
                ldsm4(sAl + (uint32_t)((wm0 + i*16 + a_row) * PAD + ks + a_k) * 2, af[i]);
            #pragma unroll
            for (int i = 0; i < 4; ++i)
                #pragma unroll
                for (int j = 0; j < 8; ++j) mma16(acc[i][j], af[i], b[j]);
        }
        __syncthreads();
    }
}

// ---- 1) QKV projection: Q split (scaled by 1/8), K hi, V hi transposed -----
__global__ __launch_bounds__(256, 1) void qkv_mma()
{
    extern __shared__ __half sm[];
    const int z = blockIdx.z;
    const __half* Ah = g_xh + (size_t)blockIdx.y * 128 * DIM;
    const __half* Al = g_xl + (size_t)blockIdx.y * 128 * DIM;
    const __half* Bh = g_wh + (size_t)z * DIM * DIM + (size_t)blockIdx.x * 256 * DIM;

    float acc[4][8][4] = {};
    gemm2(Ah, Al, Bh, sm, acc);

    const int warp = threadIdx.x >> 5, lane = threadIdx.x & 31;
    const int g = lane >> 2, t2 = (lane & 3) << 1;
    const int wm0 = (warp & 1) << 6, wn0 = (warp >> 1) << 6;
    #pragma unroll
    for (int i = 0; i < 4; ++i)
        #pragma unroll
        for (int j = 0; j < 8; ++j)
            #pragma unroll
            for (int r = 0; r < 4; ++r) {
                int m = blockIdx.y * 128 + wm0 + i * 16 + g + ((r >= 2) ? 8 : 0);
                int n = blockIdx.x * 256 + wn0 + j * 8 + t2 + (r & 1);
                int b = m >> 9, s = m & 511, h = n >> 6, d = n & 63;
                float v = acc[i][j][r];
                if (z == 0) {
                    v *= 0.125f;                       // fold 1/sqrt(hd)
                    size_t idx = ((size_t)(b * HEADS + h) * SEQ + s) * HD + d;
                    __half hh = __float2half(v);
                    g_qh[idx] = hh;
                    g_ql[idx] = __float2half(v - __half2float(hh));
                } else if (z == 1) {
                    size_t idx = ((size_t)(b * HEADS + h) * SEQ + s) * HD + d;
                    g_kh[idx] = __float2half(v);
                } else {
                    size_t idx = ((size_t)(b * HEADS + h) * HD + d) * SEQ + s;
                    g_vh[idx] = __float2half(v);
                }
            }
}

// ---- 5) out projection + bias ----------------------------------------------
__global__ __launch_bounds__(256, 1) void out_mma(const float* __restrict__ bo,
                                                  float* __restrict__ out)
{
    extern __shared__ __half sm[];
    const __half* Ah = g_ch + (size_t)blockIdx.y * 128 * DIM;
    const __half* Al = g_cl + (size_t)blockIdx.y * 128 * DIM;
    const __half* Bh = g_woh + (size_t)blockIdx.x * 256 * DIM;

    float acc[4][8][4] = {};
    gemm2(Ah, Al, Bh, sm, acc);

    const int warp = threadIdx.x >> 5, lane = threadIdx.x & 31;
    const int g = lane >> 2, t2 = (lane & 3) << 1;
    const int wm0 = (warp & 1) << 6, wn0 = (warp >> 1) << 6;
    #pragma unroll
    for (int i = 0; i < 4; ++i)
        #pragma unroll
        for (int j = 0; j < 8; ++j)
            #pragma unroll
            for (int r = 0; r < 4; ++r) {
                int m = blockIdx.y * 128 + wm0 + i * 16 + g + ((r >= 2) ? 8 : 0);
                int n = blockIdx.x * 256 + wn0 + j * 8 + t2 + (r & 1);
                out[(size_t)m * DIM + n] = acc[i][j][r] + bo[n];
            }
}

// ===========================================================================
//  fused flash attention: per (qt, bh) CTA, 8 warps x 16 query rows.
// ===========================================================================
#define FA_PADK 72
#define FA_PADV 136
#define FA_KH   (128*FA_PADK)            /* halves */
#define FA_VT   (64*FA_PADV)
#define FA_STAGE_H (FA_KH + FA_VT)
#define FA_Q_H  (2*128*FA_PADK)
#define FA_SMEM ((FA_Q_H + 2*FA_STAGE_H)*2)   /* 108544 B */

__global__ __launch_bounds__(256) void flash_attn()
{
    extern __shared__ __half fsm[];
    const int qt = blockIdx.x, bh = blockIdx.y;
    const int tid = threadIdx.x, warp = tid >> 5, lane = tid & 31;
    const int g = lane >> 2, t2 = (lane & 3) << 1;
    const int a_row = (lane & 7) + ((lane >> 3) & 1) * 8;
    const int a_k   = ((lane >> 4) & 1) * 8;
    const int b_row = (lane & 7) + ((lane >> 4) & 1) * 8;
    const int b_k   = ((lane >> 3) & 1) * 8;

    const int NT[4] = {2, 2, 3, 4};
    const int ntiles = NT[qt];

    const __half* Qh = g_qh + ((size_t)bh * SEQ + qt * 128) * HD;
    const __half* Ql = g_ql + ((size_t)bh * SEQ + qt * 128) * HD;
    const __half* Kh = g_kh + (size_t)bh * SEQ * HD;
    const __half* Vt = g_vh + (size_t)bh * HD * SEQ;

    const uint32_t sb  = smem_u32(fsm);
    const uint32_t sQh = sb;
    const uint32_t sQl = sb + (uint32_t)128 * FA_PADK * 2;
    const uint32_t sStg = sb + (uint32_t)FA_Q_H * 2;

    #pragma unroll
    for (int c = 0; c < 4; ++c) {
        int idx = tid + c * 256;
        int row = idx >> 3, ch = idx & 7;
        cp_async16(sQh + (uint32_t)(row * FA_PADK + ch * 8) * 2, Qh + (size_t)row * HD + ch * 8);
        cp_async16(sQl + (uint32_t)(row * FA_PADK + ch * 8) * 2, Ql + (size_t)row * HD + ch * 8);
    }
    asm volatile("cp.async.commit_group;\n" ::: "memory");

    auto load_kv = [&](int t, int s) {
        uint32_t st = sStg + (uint32_t)s * FA_STAGE_H * 2;
        #pragma unroll
        for (int c = 0; c < 4; ++c) {
            int idx = tid + c * 256;
            int row = idx >> 3, ch = idx & 7;
            cp_async16(st + (uint32_t)(row * FA_PADK + ch * 8) * 2,
                       Kh + (size_t)(t * 128 + row) * HD + ch * 8);
        }
        uint32_t sv = st + (uint32_t)FA_KH * 2;
        #pragma unroll
        for (int c = 0; c < 4; ++c) {
            int idx = tid + c * 256;
            int row = idx >> 4, ch = idx & 15;
            cp_async16(sv + (uint32_t)(row * FA_PADV + ch * 8) * 2,
                       Vt + (size_t)row * SEQ + t * 128 + ch * 8);
        }
    };

    load_kv(0, 0);
    asm volatile("cp.async.commit_group;\n" ::: "memory");

    asm volatile("cp.async.wait_group 1;\n" ::: "memory");
    __syncthreads();
    uint32_t qfh[4][4], qfl[4][4];
    #pragma unroll
    for (int ks = 0; ks < 4; ++ks) {
        ldsm4(sQh + (uint32_t)((warp * 16 + a_row) * FA_PADK + ks * 16 + a_k) * 2, qfh[ks]);
        ldsm4(sQl + (uint32_t)((warp * 16 + a_row) * FA_PADK + ks * 16 + a_k) * 2, qfl[ks]);
    }

    float acc_o[8][4] = {};
    float m0 = neg_inf(), m1 = neg_inf(), l0 = 0.f, l1 = 0.f;

    for (int t = 0; t < ntiles; ++t) {
        if (t + 1 < ntiles) {
            load_kv(t + 1, (t + 1) & 1);
            asm volatile("cp.async.commit_group;\n" ::: "memory");
            asm volatile("cp.async.wait_group 1;\n" ::: "memory");
        } else {
            asm volatile("cp.async.wait_group 0;\n" ::: "memory");
        }
        __syncthreads();

        const uint32_t st = sStg + (uint32_t)(t & 1) * FA_STAGE_H * 2;
        const uint32_t sK = st;
        const uint32_t sV = st + (uint32_t)FA_KH * 2;

        // ---- S = Q K^T (2-term), warp tile 16x128 ----
        float s[16][4];
        #pragma unroll
        for (int j = 0; j < 16; ++j)
            #pragma unroll
            for (int r = 0; r < 4; ++r) s[j][r] = 0.f;

        #pragma unroll
        for (int ks = 0; ks < 4; ++ks) {
            uint32_t bfr[16][2];
            #pragma unroll
            for (int jj = 0; jj < 8; ++jj) {
                uint32_t r[4];
                ldsm4(sK + (uint32_t)((jj*16 + b_row) * FA_PADK + ks*16 + b_k) * 2, r);
                bfr[jj*2+0][0] = r[0]; bfr[jj*2+0][1] = r[1];
                bfr[jj*2+1][0] = r[2]; bfr[jj*2+1][1] = r[3];
            }
            #pragma unroll
            for (int j = 0; j < 16; ++j) {
                mma16(s[j], qfh[ks], bfr[j]);
                mma16(s[j], qfl[ks], bfr[j]);
            }
        }

        if (t == ntiles - 1) {
            const int q0 = qt * 128 + warp * 16 + g, q1 = q0 + 8;
            #pragma unroll
            for (int j = 0; j < 16; ++j) {
                int k0 = t * 128 + j * 8 + t2;
                if (!okqk(q0, k0))     s[j][0] = neg_inf();
                if (!okqk(q0, k0 + 1)) s[j][1] = neg_inf();
                if (!okqk(q1, k0))     s[j][2] = neg_inf();
                if (!okqk(q1, k0 + 1)) s[j][3] = neg_inf();
            }
        }

        // ---- online softmax ----
        float mx0 = neg_inf(), mx1 = neg_inf();
        #pragma unroll
        for (int j = 0; j < 16; ++j) {
            mx0 = fmaxf(mx0, fmaxf(s[j][0], s[j][1]));
            mx1 = fmaxf(mx1, fmaxf(s[j][2], s[j][3]));
        }
        mx0 = fmaxf(mx0, __shfl_xor_sync(0xffffffffu, mx0, 1));
        mx0 = fmaxf(mx0, __shfl_xor_sync(0xffffffffu, mx0, 2));
        mx1 = fmaxf(mx1, __shfl_xor_sync(0xffffffffu, mx1, 1));
        mx1 = fmaxf(mx1, __shfl_xor_sync(0xffffffffu, mx1, 2));

        const float mn0 = fmaxf(m0, mx0), mn1 = fmaxf(m1, mx1);
        const float sc0 = __expf(m0 - mn0), sc1 = __expf(m1 - mn1);
        m0 = mn0; m1 = mn1;

        float sum0 = 0.f, sum1 = 0.f;
        #pragma unroll
        for (int j = 0; j < 16; ++j) {
            s[j][0] = __expf(s[j][0] - mn0); sum0 += s[j][0];
            s[j][1] = __expf(s[j][1] - mn0); sum0 += s[j][1];
            s[j][2] = __expf(s[j][2] - mn1); sum1 += s[j][2];
            s[j][3] = __expf(s[j][3] - mn1); sum1 += s[j][3];
        }
        sum0 += __shfl_xor_sync(0xffffffffu, sum0, 1);
        sum0 += __shfl_xor_sync(0xffffffffu, sum0, 2);
        sum1 += __shfl_xor_sync(0xffffffffu, sum1, 1);
        sum1 += __shfl_xor_sync(0xffffffffu, sum1, 2);
        l0 = l0 * sc0 + sum0;
        l1 = l1 * sc1 + sum1;

        #pragma unroll
        for (int jn = 0; jn < 8; ++jn) {
            acc_o[jn][0] *= sc0; acc_o[jn][1] *= sc0;
            acc_o[jn][2] *= sc1; acc_o[jn][3] *= sc1;
        }

        // ---- O += P V (P split hi/lo, in-register repack) ----
        #pragma unroll
        for (int ks = 0; ks < 8; ++ks) {
            uint32_t bv[8][2];
            #pragma unroll
            for (int jj = 0; jj < 4; ++jj) {
                uint32_t r[4];
                ldsm4(sV + (uint32_t)((jj*16 + b_row) * FA_PADV + ks*16 + b_k) * 2, r);
                bv[jj*2+0][0] = r[0]; bv[jj*2+0][1] = r[1];
                bv[jj*2+1][0] = r[2]; bv[jj*2+1][1] = r[3];
            }
            uint32_t pah[4], pal[4];
            #pragma unroll
            for (int half = 0; half < 2; ++half) {
                const float* ps = s[2*ks + half];
                __half h0 = __float2half(ps[0]), h1 = __float2half(ps[1]);
                __half h2 = __float2half(ps[2]), h3 = __float2half(ps[3]);
                __half2 ah = __halves2half2(h0, h1);
                __half2 bhv = __halves2half2(h2, h3);
                __half2 al = __halves2half2(__float2half(ps[0] - __half2float(h0)),
                                            __float2half(ps[1] - __half2float(h1)));
                __half2 bl = __halves2half2(__float2half(ps[2] - __half2float(h2)),
                                            __float2half(ps[3] - __half2float(h3)));
                pah[half*2+0] = *reinterpret_cast<uint32_t*>(&ah);
                pah[half*2+1] = *reinterpret_cast<uint32_t*>(&bhv);
                pal[half*2+0] = *reinterpret_cast<uint32_t*>(&al);
                pal[half*2+1] = *reinterpret_cast<uint32_t*>(&bl);
            }
            #pragma unroll
            for (int jn = 0; jn < 8; ++jn) {
                mma16(acc_o[jn], pah, bv[jn]);
                mma16(acc_o[jn], pal, bv[jn]);
            }
        }
        __syncthreads();
    }

    const float il0 = __frcp_rn(l0), il1 = __frcp_rn(l1);
    const int b = bh >> 4, h = bh & 15;
    const int q0 = qt * 128 + warp * 16 + g;
    #pragma unroll
    for (int jn = 0; jn < 8; ++jn)
        #pragma unroll
        for (int r = 0; r < 4; ++r) {
            int q = (r >= 2) ? q0 + 8 : q0;
            float v = acc_o[jn][r] * ((r >= 2) ? il1 : il0);
            int n = jn * 8 + t2 + (r & 1);
            size_t idx = ((size_t)(b * SEQ + q) * DIM) + h * HD + n;
            __half hh = __float2half(v);
            g_ch[idx] = hh;
            g_cl[idx] = __float2half(v - __half2float(hh));
        }
}

// ===========================================================================
extern "C" void kernel_launch(void* const* d_in, const int* in_sizes, int n_in,
                              void* d_out, int out_size)
{
    const float* x  = (const float*)d_in[0];
    const float* wq = (const float*)d_in[1];
    const float* wk = (const float*)d_in[2];
    const float* wv = (const float*)d_in[3];
    const float* wo = (const float*)d_in[4];
    const float* bo = (const float*)d_in[5];
    float* out = (float*)d_out;

    static bool attr_set = false;
    if (!attr_set) {
        cudaFuncSetAttribute(qkv_mma,    cudaFuncAttributeMaxDynamicSharedMemorySize, PRJ_SMEM);
        cudaFuncSetAttribute(out_mma,    cudaFuncAttributeMaxDynamicSharedMemorySize, PRJ_SMEM);
        cudaFuncSetAttribute(flash_attn, cudaFuncAttributeMaxDynamicSharedMemorySize, FA_SMEM);
        attr_set = true;
    }

    split_x<<<MROWS*DIM/4/256, 256>>>(x);
    split_w<<<dim3(DIM*DIM/4/256, 4), 256>>>(wq, wk, wv, wo);

    qkv_mma   <<<dim3(DIM/256, MROWS/128, 3), 256, PRJ_SMEM>>>();
    flash_attn<<<dim3(SEQ/128, BH), 256, FA_SMEM>>>();
    out_mma   <<<dim3(DIM/256, MROWS/128), 256, PRJ_SMEM>>>(bo, out);
}

// round 8
// speedup vs baseline: 5.7537x; 1.4111x over previous
#include <cuda_runtime.h>
#include <cuda_fp16.h>
#include <cstdint>

#define BATCH   8
#define SEQ     512
#define DIM     1024
#define HEADS   16
#define HD      64
#define NPATCH  196
#define MROWS   (BATCH*SEQ)     /* 4096 */
#define BH      (BATCH*HEADS)   /* 128  */

// ---------------- scratch (device globals: allocation-free) ----------------
__device__ __half g_xh [(size_t)MROWS*DIM];          // x hi
__device__ __half g_wh [(size_t)3*DIM*DIM];          // wq,wk,wv hi
__device__ __half g_woh[(size_t)DIM*DIM];            // wo hi
__device__ __half g_qh [(size_t)BH*SEQ*HD];          // Q split (pre-scaled by 1/8)
__device__ __half g_ql [(size_t)BH*SEQ*HD];
__device__ __half g_kh [(size_t)BH*SEQ*HD];          // K hi
__device__ __half g_vh [(size_t)BH*HD*SEQ];          // V hi, [B,H,hd,S]
__device__ __half g_ch [(size_t)MROWS*DIM];          // ctx hi [B,S,D]

__device__ __forceinline__ float neg_inf() { return __int_as_float(0xff800000); }
__device__ __forceinline__ bool okqk(int q, int k)
{ return (q < NPATCH) ? (k < NPATCH) : (k <= q); }

// ===========================================================================
//  split / convert kernels
// ===========================================================================
__global__ __launch_bounds__(256) void split_x(const float* __restrict__ x)
{
    size_t i = (size_t)blockIdx.x * 256 + threadIdx.x;
    float4 v = ((const float4*)x)[i];
    ((__half2*)g_xh)[i*2+0] = __halves2half2(__float2half(v.x), __float2half(v.y));
    ((__half2*)g_xh)[i*2+1] = __halves2half2(__float2half(v.z), __float2half(v.w));
}

__global__ __launch_bounds__(256) void split_w(const float* __restrict__ wq,
                                               const float* __restrict__ wk,
                                               const float* __restrict__ wv,
                                               const float* __restrict__ wo)
{
    int seg = blockIdx.y;
    const float* src = (seg == 0) ? wq : (seg == 1) ? wk : (seg == 2) ? wv : wo;
    __half* hi = (seg < 3) ? g_wh + (size_t)seg * DIM * DIM : g_woh;
    size_t i = (size_t)blockIdx.x * 256 + threadIdx.x;
    float4 v = ((const float4*)src)[i];
    ((__half2*)hi)[i*2+0] = __halves2half2(__float2half(v.x), __float2half(v.y));
    ((__half2*)hi)[i*2+1] = __halves2half2(__float2half(v.z), __float2half(v.w));
}

// ===========================================================================
//  common utils
// ===========================================================================
__device__ __forceinline__ uint32_t smem_u32(const void* p)
{ return (uint32_t)__cvta_generic_to_shared(p); }

__device__ __forceinline__ void cp_async16(uint32_t s, const void* g)
{ asm volatile("cp.async.cg.shared.global [%0], [%1], 16;\n" :: "r"(s), "l"(g)); }

__device__ __forceinline__ void ldsm4(uint32_t addr, uint32_t* r)
{
    asm volatile("ldmatrix.sync.aligned.m8n8.x4.shared.b16 {%0,%1,%2,%3}, [%4];"
                 : "=r"(r[0]), "=r"(r[1]), "=r"(r[2]), "=r"(r[3]) : "r"(addr));
}

__device__ __forceinline__ void mma16(float* c, const uint32_t* a, const uint32_t* b)
{
    asm volatile(
        "mma.sync.aligned.m16n8k16.row.col.f32.f16.f16.f32 "
        "{%0,%1,%2,%3},{%4,%5,%6,%7},{%8,%9},{%0,%1,%2,%3};"
        : "+f"(c[0]), "+f"(c[1]), "+f"(c[2]), "+f"(c[3])
        : "r"(a[0]), "r"(a[1]), "r"(a[2]), "r"(a[3]), "r"(b[0]), "r"(b[1]));
}

// ===========================================================================
//  1-term fp16 128x256xK GEMM (projections). 3-stage cp.async pipeline.
//  8 warps 2(M)x4(N), warp tile 64x64.
// ===========================================================================
#define BK       32
#define PAD      40
#define A_TEH    (128*PAD)          /* halves per A tile  */
#define B_TEH    (256*PAD)          /* halves per B tile  */
#define STAGE_H  (A_TEH + B_TEH)    /* 15360 halves       */
#define PRJ_SMEM (3*STAGE_H*2)      /* 92160 bytes        */
#define PRJ_NKT  (DIM/BK)           /* 32                 */

__device__ __forceinline__ void gemm1(
    const __half* __restrict__ Ah, const __half* __restrict__ Bh,
    __half* sm, float (&acc)[4][8][4])
{
    const int tid  = threadIdx.x;
    const int warp = tid >> 5, lane = tid & 31;
    const int wm0  = (warp & 1) << 6;       // 0/64
    const int wn0  = (warp >> 1) << 6;      // 0,64,128,192
    const int a_row = (lane & 7) + ((lane >> 3) & 1) * 8;
    const int a_k   = ((lane >> 4) & 1) * 8;
    const int b_row = (lane & 7) + ((lane >> 4) & 1) * 8;
    const int b_k   = ((lane >> 3) & 1) * 8;
    const uint32_t sb = smem_u32(sm);

    auto load_stage = [&](int kt, int s) {
        uint32_t st = sb + (uint32_t)s * STAGE_H * 2;
        #pragma unroll
        for (int c = 0; c < 2; ++c) {
            int idx = tid + c * 256;
            int row = idx >> 2, ch = idx & 3;
            cp_async16(st + (uint32_t)(row * PAD + ch * 8) * 2,
                       Ah + (size_t)row * DIM + kt * BK + ch * 8);
        }
        uint32_t bb = st + (uint32_t)A_TEH * 2;
        #pragma unroll
        for (int c = 0; c < 4; ++c) {
            int idx = tid + c * 256;
            int row = idx >> 2, ch = idx & 3;
            cp_async16(bb + (uint32_t)(row * PAD + ch * 8) * 2,
                       Bh + (size_t)row * DIM + kt * BK + ch * 8);
        }
    };

    load_stage(0, 0);
    asm volatile("cp.async.commit_group;\n" ::: "memory");
    load_stage(1, 1);
    asm volatile("cp.async.commit_group;\n" ::: "memory");

    for (int kt = 0; kt < PRJ_NKT; ++kt) {
        const int cur = kt % 3;
        if (kt + 2 < PRJ_NKT) {
            load_stage(kt + 2, (kt + 2) % 3);
            asm volatile("cp.async.commit_group;\n" ::: "memory");
            asm volatile("cp.async.wait_group 2;\n" ::: "memory");
        } else if (kt + 1 < PRJ_NKT) {
            asm volatile("cp.async.wait_group 1;\n" ::: "memory");
        } else {
            asm volatile("cp.async.wait_group 0;\n" ::: "memory");
        }
        __syncthreads();

        const uint32_t st  = sb + (uint32_t)cur * STAGE_H * 2;
        const uint32_t sAh = st;
        const uint32_t sBh = st + A_TEH * 2;

        #pragma unroll
        for (int ks = 0; ks < BK; ks += 16) {
            uint32_t b[8][2];
            #pragma unroll
            for (int jj = 0; jj < 4; ++jj) {
                uint32_t r[4];
                ldsm4(sBh + (uint32_t)((wn0 + jj*16 + b_row) * PAD + ks + b_k) * 2, r);
                b[jj*2+0][0] = r[0]; b[jj*2+0][1] = r[1];
                b[jj*2+1][0] = r[2]; b[jj*2+1][1] = r[3];
            }
            uint32_t af[4][4];
            #pragma unroll
            for (int i = 0; i < 4; ++i)
                ldsm4(sAh + (uint32_t)((wm0 + i*16 + a_row) * PAD + ks + a_k) * 2, af[i]);
            #pragma unroll
            for (int i = 0; i < 4; ++i)
                #pragma unroll
                for (int j = 0; j < 8; ++j) mma16(acc[i][j], af[i], b[j]);
        }
        __syncthreads();
    }
}

// ---- 1) QKV projection: Q split (scaled by 1/8), K hi, V hi transposed -----
__global__ __launch_bounds__(256, 1) void qkv_mma()
{
    extern __shared__ __half sm[];
    const int z = blockIdx.z;
    const __half* Ah = g_xh + (size_t)blockIdx.y * 128 * DIM;
    const __half* Bh = g_wh + (size_t)z * DIM * DIM + (size_t)blockIdx.x * 256 * DIM;

    float acc[4][8][4] = {};
    gemm1(Ah, Bh, sm, acc);

    const int warp = threadIdx.x >> 5, lane = threadIdx.x & 31;
    const int g = lane >> 2, t2 = (lane & 3) << 1;
    const int wm0 = (warp & 1) << 6, wn0 = (warp >> 1) << 6;
    #pragma unroll
    for (int i = 0; i < 4; ++i)
        #pragma unroll
        for (int j = 0; j < 8; ++j)
            #pragma unroll
            for (int r = 0; r < 4; ++r) {
                int m = blockIdx.y * 128 + wm0 + i * 16 + g + ((r >= 2) ? 8 : 0);
                int n = blockIdx.x * 256 + wn0 + j * 8 + t2 + (r & 1);
                int b = m >> 9, s = m & 511, h = n >> 6, d = n & 63;
                float v = acc[i][j][r];
                if (z == 0) {
                    v *= 0.125f;                       // fold 1/sqrt(hd)
                    size_t idx = ((size_t)(b * HEADS + h) * SEQ + s) * HD + d;
                    __half hh = __float2half(v);
                    g_qh[idx] = hh;
                    g_ql[idx] = __float2half(v - __half2float(hh));
                } else if (z == 1) {
                    size_t idx = ((size_t)(b * HEADS + h) * SEQ + s) * HD + d;
                    g_kh[idx] = __float2half(v);
                } else {
                    size_t idx = ((size_t)(b * HEADS + h) * HD + d) * SEQ + s;
                    g_vh[idx] = __float2half(v);
                }
            }
}

// ---- 5) out projection + bias ----------------------------------------------
__global__ __launch_bounds__(256, 1) void out_mma(const float* __restrict__ bo,
                                                  float* __restrict__ out)
{
    extern __shared__ __half sm[];
    const __half* Ah = g_ch + (size_t)blockIdx.y * 128 * DIM;
    const __half* Bh = g_woh + (size_t)blockIdx.x * 256 * DIM;

    float acc[4][8][4] = {};
    gemm1(Ah, Bh, sm, acc);

    const int warp = threadIdx.x >> 5, lane = threadIdx.x & 31;
    const int g = lane >> 2, t2 = (lane & 3) << 1;
    const int wm0 = (warp & 1) << 6, wn0 = (warp >> 1) << 6;
    #pragma unroll
    for (int i = 0; i < 4; ++i)
        #pragma unroll
        for (int j = 0; j < 8; ++j)
            #pragma unroll
            for (int r = 0; r < 4; ++r) {
                int m = blockIdx.y * 128 + wm0 + i * 16 + g + ((r >= 2) ? 8 : 0);
                int n = blockIdx.x * 256 + wn0 + j * 8 + t2 + (r & 1);
                out[(size_t)m * DIM + n] = acc[i][j][r] + bo[n];
            }
}

// ===========================================================================
//  fused flash attention: per (qt, bh) CTA, 8 warps x 16 query rows.
//  S = Qsplit·Kh (2-term), online softmax fp32, O += Phi·Vh (1-term).
// ===========================================================================
#define FA_PADK 72
#define FA_PADV 136
#define FA_KH   (128*FA_PADK)            /* halves */
#define FA_VT   (64*FA_PADV)
#define FA_STAGE_H (FA_KH + FA_VT)
#define FA_Q_H  (2*128*FA_PADK)
#define FA_SMEM ((FA_Q_H + 2*FA_STAGE_H)*2)   /* 108544 B */

__global__ __launch_bounds__(256) void flash_attn()
{
    extern __shared__ __half fsm[];
    const int qt = blockIdx.x, bh = blockIdx.y;
    const int tid = threadIdx.x, warp = tid >> 5, lane = tid & 31;
    const int g = lane >> 2, t2 = (lane & 3) << 1;
    const int a_row = (lane & 7) + ((lane >> 3) & 1) * 8;
    const int a_k   = ((lane >> 4) & 1) * 8;
    const int b_row = (lane & 7) + ((lane >> 4) & 1) * 8;
    const int b_k   = ((lane >> 3) & 1) * 8;

    const int NT[4] = {2, 2, 3, 4};
    const int ntiles = NT[qt];

    const __half* Qh = g_qh + ((size_t)bh * SEQ + qt * 128) * HD;
    const __half* Ql = g_ql + ((size_t)bh * SEQ + qt * 128) * HD;
    const __half* Kh = g_kh + (size_t)bh * SEQ * HD;
    const __half* Vt = g_vh + (size_t)bh * HD * SEQ;

    const uint32_t sb  = smem_u32(fsm);
    const uint32_t sQh = sb;
    const uint32_t sQl = sb + (uint32_t)128 * FA_PADK * 2;
    const uint32_t sStg = sb + (uint32_t)FA_Q_H * 2;

    #pragma unroll
    for (int c = 0; c < 4; ++c) {
        int idx = tid + c * 256;
        int row = idx >> 3, ch = idx & 7;
        cp_async16(sQh + (uint32_t)(row * FA_PADK + ch * 8) * 2, Qh + (size_t)row * HD + ch * 8);
        cp_async16(sQl + (uint32_t)(row * FA_PADK + ch * 8) * 2, Ql + (size_t)row * HD + ch * 8);
    }
    asm volatile("cp.async.commit_group;\n" ::: "memory");

    auto load_kv = [&](int t, int s) {
        uint32_t st = sStg + (uint32_t)s * FA_STAGE_H * 2;
        #pragma unroll
        for (int c = 0; c < 4; ++c) {
            int idx = tid + c * 256;
            int row = idx >> 3, ch = idx & 7;
            cp_async16(st + (uint32_t)(row * FA_PADK + ch * 8) * 2,
                       Kh + (size_t)(t * 128 + row) * HD + ch * 8);
        }
        uint32_t sv = st + (uint32_t)FA_KH * 2;
        #pragma unroll
        for (int c = 0; c < 4; ++c) {
            int idx = tid + c * 256;
            int row = idx >> 4, ch = idx & 15;
            cp_async16(sv + (uint32_t)(row * FA_PADV + ch * 8) * 2,
                       Vt + (size_t)row * SEQ + t * 128 + ch * 8);
        }
    };

    load_kv(0, 0);
    asm volatile("cp.async.commit_group;\n" ::: "memory");

    asm volatile("cp.async.wait_group 1;\n" ::: "memory");
    __syncthreads();
    uint32_t qfh[4][4], qfl[4][4];
    #pragma unroll
    for (int ks = 0; ks < 4; ++ks) {
        ldsm4(sQh + (uint32_t)((warp * 16 + a_row) * FA_PADK + ks * 16 + a_k) * 2, qfh[ks]);
        ldsm4(sQl + (uint32_t)((warp * 16 + a_row) * FA_PADK + ks * 16 + a_k) * 2, qfl[ks]);
    }

    float acc_o[8][4] = {};
    float m0 = neg_inf(), m1 = neg_inf(), l0 = 0.f, l1 = 0.f;

    for (int t = 0; t < ntiles; ++t) {
        if (t + 1 < ntiles) {
            load_kv(t + 1, (t + 1) & 1);
            asm volatile("cp.async.commit_group;\n" ::: "memory");
            asm volatile("cp.async.wait_group 1;\n" ::: "memory");
        } else {
            asm volatile("cp.async.wait_group 0;\n" ::: "memory");
        }
        __syncthreads();

        const uint32_t st = sStg + (uint32_t)(t & 1) * FA_STAGE_H * 2;
        const uint32_t sK = st;
        const uint32_t sV = st + (uint32_t)FA_KH * 2;

        // ---- S = Q K^T (2-term), warp tile 16x128 ----
        float s[16][4];
        #pragma unroll
        for (int j = 0; j < 16; ++j)
            #pragma unroll
            for (int r = 0; r < 4; ++r) s[j][r] = 0.f;

        #pragma unroll
        for (int ks = 0; ks < 4; ++ks) {
            uint32_t bfr[16][2];
            #pragma unroll
            for (int jj = 0; jj < 8; ++jj) {
                uint32_t r[4];
                ldsm4(sK + (uint32_t)((jj*16 + b_row) * FA_PADK + ks*16 + b_k) * 2, r);
                bfr[jj*2+0][0] = r[0]; bfr[jj*2+0][1] = r[1];
                bfr[jj*2+1][0] = r[2]; bfr[jj*2+1][1] = r[3];
            }
            #pragma unroll
            for (int j = 0; j < 16; ++j) {
                mma16(s[j], qfh[ks], bfr[j]);
                mma16(s[j], qfl[ks], bfr[j]);
            }
        }

        if (t == ntiles - 1) {
            const int q0 = qt * 128 + warp * 16 + g, q1 = q0 + 8;
            #pragma unroll
            for (int j = 0; j < 16; ++j) {
                int k0 = t * 128 + j * 8 + t2;
                if (!okqk(q0, k0))     s[j][0] = neg_inf();
                if (!okqk(q0, k0 + 1)) s[j][1] = neg_inf();
                if (!okqk(q1, k0))     s[j][2] = neg_inf();
                if (!okqk(q1, k0 + 1)) s[j][3] = neg_inf();
            }
        }

        // ---- online softmax ----
        float mx0 = neg_inf(), mx1 = neg_inf();
        #pragma unroll
        for (int j = 0; j < 16; ++j) {
            mx0 = fmaxf(mx0, fmaxf(s[j][0], s[j][1]));
            mx1 = fmaxf(mx1, fmaxf(s[j][2], s[j][3]));
        }
        mx0 = fmaxf(mx0, __shfl_xor_sync(0xffffffffu, mx0, 1));
        mx0 = fmaxf(mx0, __shfl_xor_sync(0xffffffffu, mx0, 2));
        mx1 = fmaxf(mx1, __shfl_xor_sync(0xffffffffu, mx1, 1));
        mx1 = fmaxf(mx1, __shfl_xor_sync(0xffffffffu, mx1, 2));

        const float mn0 = fmaxf(m0, mx0), mn1 = fmaxf(m1, mx1);
        const float sc0 = __expf(m0 - mn0), sc1 = __expf(m1 - mn1);
        m0 = mn0; m1 = mn1;

        float sum0 = 0.f, sum1 = 0.f;
        #pragma unroll
        for (int j = 0; j < 16; ++j) {
            s[j][0] = __expf(s[j][0] - mn0); sum0 += s[j][0];
            s[j][1] = __expf(s[j][1] - mn0); sum0 += s[j][1];
            s[j][2] = __expf(s[j][2] - mn1); sum1 += s[j][2];
            s[j][3] = __expf(s[j][3] - mn1); sum1 += s[j][3];
        }
        sum0 += __shfl_xor_sync(0xffffffffu, sum0, 1);
        sum0 += __shfl_xor_sync(0xffffffffu, sum0, 2);
        sum1 += __shfl_xor_sync(0xffffffffu, sum1, 1);
        sum1 += __shfl_xor_sync(0xffffffffu, sum1, 2);
        l0 = l0 * sc0 + sum0;
        l1 = l1 * sc1 + sum1;

        #pragma unroll
        for (int jn = 0; jn < 8; ++jn) {
            acc_o[jn][0] *= sc0; acc_o[jn][1] *= sc0;
            acc_o[jn][2] *= sc1; acc_o[jn][3] *= sc1;
        }

        // ---- O += P V (P hi only) ----
        #pragma unroll
        for (int ks = 0; ks < 8; ++ks) {
            uint32_t bv[8][2];
            #pragma unroll
            for (int jj = 0; jj < 4; ++jj) {
                uint32_t r[4];
                ldsm4(sV + (uint32_t)((jj*16 + b_row) * FA_PADV + ks*16 + b_k) * 2, r);
                bv[jj*2+0][0] = r[0]; bv[jj*2+0][1] = r[1];
                bv[jj*2+1][0] = r[2]; bv[jj*2+1][1] = r[3];
            }
            uint32_t pah[4];
            #pragma unroll
            for (int half = 0; half < 2; ++half) {
                const float* ps = s[2*ks + half];
                __half2 ah  = __halves2half2(__float2half(ps[0]), __float2half(ps[1]));
                __half2 bhv = __halves2half2(__float2half(ps[2]), __float2half(ps[3]));
                pah[half*2+0] = *reinterpret_cast<uint32_t*>(&ah);
                pah[half*2+1] = *reinterpret_cast<uint32_t*>(&bhv);
            }
            #pragma unroll
            for (int jn = 0; jn < 8; ++jn)
                mma16(acc_o[jn], pah, bv[jn]);
        }
        __syncthreads();
    }

    const float il0 = __frcp_rn(l0), il1 = __frcp_rn(l1);
    const int b = bh >> 4, h = bh & 15;
    const int q0 = qt * 128 + warp * 16 + g;
    #pragma unroll
    for (int jn = 0; jn < 8; ++jn)
        #pragma unroll
        for (int r = 0; r < 4; ++r) {
            int q = (r >= 2) ? q0 + 8 : q0;
            float v = acc_o[jn][r] * ((r >= 2) ? il1 : il0);
            int n = jn * 8 + t2 + (r & 1);
            size_t idx = ((size_t)(b * SEQ + q) * DIM) + h * HD + n;
            g_ch[idx] = __float2half(v);
        }
}

// ===========================================================================
extern "C" void kernel_launch(void* const* d_in, const int* in_sizes, int n_in,
                              void* d_out, int out_size)
{
    const float* x  = (const float*)d_in[0];
    const float* wq = (const float*)d_in[1];
    const float* wk = (const float*)d_in[2];
    const float* wv = (const float*)d_in[3];
    const float* wo = (const float*)d_in[4];
    const float* bo = (const float*)d_in[5];
    float* out = (float*)d_out;

    static bool attr_set = false;
    if (!attr_set) {
        cudaFuncSetAttribute(qkv_mma,    cudaFuncAttributeMaxDynamicSharedMemorySize, PRJ_SMEM);
        cudaFuncSetAttribute(out_mma,    cudaFuncAttributeMaxDynamicSharedMemorySize, PRJ_SMEM);
        cudaFuncSetAttribute(flash_attn, cudaFuncAttributeMaxDynamicSharedMemorySize, FA_SMEM);
        attr_set = true;
    }

    split_x<<<MROWS*DIM/4/256, 256>>>(x);
    split_w<<<dim3(DIM*DIM/4/256, 4), 256>>>(wq, wk, wv, wo);

    qkv_mma   <<<dim3(DIM/256, MROWS/128, 3), 256, PRJ_SMEM>>>();
    flash_attn<<<dim3(SEQ/128, BH), 256, FA_SMEM>>>();
    out_mma   <<<dim3(DIM/256, MROWS/128), 256, PRJ_SMEM>>>(bo, out);
}

// round 9
// speedup vs baseline: 6.4369x; 1.1187x over previous
#include <cuda_runtime.h>
#include <cuda_fp16.h>
#include <cstdint>

#define BATCH   8
#define SEQ     512
#define DIM     1024
#define HEADS   16
#define HD      64
#define NPATCH  196
#define MROWS   (BATCH*SEQ)     /* 4096 */
#define BH      (BATCH*HEADS)   /* 128  */

// ---------------- scratch (device globals: allocation-free) ----------------
__device__ __half g_xh [(size_t)MROWS*DIM];          // x hi
__device__ __half g_wh [(size_t)3*DIM*DIM];          // wq,wk,wv hi
__device__ __half g_woh[(size_t)DIM*DIM];            // wo hi
__device__ __half g_qh [(size_t)BH*SEQ*HD];          // Q hi (pre-scaled by 1/8)
__device__ __half g_kh [(size_t)BH*SEQ*HD];          // K hi
__device__ __half g_vh [(size_t)BH*HD*SEQ];          // V hi, [B,H,hd,S]
__device__ __half g_ch [(size_t)MROWS*DIM];          // ctx hi [B,S,D]

__device__ __forceinline__ float neg_inf() { return __int_as_float(0xff800000); }
__device__ __forceinline__ bool okqk(int q, int k)
{ return (q < NPATCH) ? (k < NPATCH) : (k <= q); }

// ===========================================================================
//  fused split kernel: x (4096 blocks) + 4 weights (1024 blocks each)
// ===========================================================================
__global__ __launch_bounds__(256) void split_all(const float* __restrict__ x,
                                                 const float* __restrict__ wq,
                                                 const float* __restrict__ wk,
                                                 const float* __restrict__ wv,
                                                 const float* __restrict__ wo)
{
    const float* src;
    __half* dst;
    size_t i;
    if (blockIdx.x < 4096) {
        src = x; dst = g_xh;
        i = (size_t)blockIdx.x * 256 + threadIdx.x;
    } else {
        int w = blockIdx.x - 4096;
        int seg = w >> 10;
        src = (seg == 0) ? wq : (seg == 1) ? wk : (seg == 2) ? wv : wo;
        dst = (seg < 3) ? g_wh + (size_t)seg * DIM * DIM : g_woh;
        i = (size_t)(w & 1023) * 256 + threadIdx.x;
    }
    float4 v = ((const float4*)src)[i];
    ((__half2*)dst)[i*2+0] = __halves2half2(__float2half(v.x), __float2half(v.y));
    ((__half2*)dst)[i*2+1] = __halves2half2(__float2half(v.z), __float2half(v.w));
}

// ===========================================================================
//  common utils
// ===========================================================================
__device__ __forceinline__ uint32_t smem_u32(const void* p)
{ return (uint32_t)__cvta_generic_to_shared(p); }

__device__ __forceinline__ void cp_async16(uint32_t s, const void* g)
{ asm volatile("cp.async.cg.shared.global [%0], [%1], 16;\n" :: "r"(s), "l"(g)); }

__device__ __forceinline__ void ldsm4(uint32_t addr, uint32_t* r)
{
    asm volatile("ldmatrix.sync.aligned.m8n8.x4.shared.b16 {%0,%1,%2,%3}, [%4];"
                 : "=r"(r[0]), "=r"(r[1]), "=r"(r[2]), "=r"(r[3]) : "r"(addr));
}

__device__ __forceinline__ void mma16(float* c, const uint32_t* a, const uint32_t* b)
{
    asm volatile(
        "mma.sync.aligned.m16n8k16.row.col.f32.f16.f16.f32 "
        "{%0,%1,%2,%3},{%4,%5,%6,%7},{%8,%9},{%0,%1,%2,%3};"
        : "+f"(c[0]), "+f"(c[1]), "+f"(c[2]), "+f"(c[3])
        : "r"(a[0]), "r"(a[1]), "r"(a[2]), "r"(a[3]), "r"(b[0]), "r"(b[1]));
}

// ===========================================================================
//  1-term fp16 128x256xK GEMM (projections). 3-stage cp.async pipeline.
//  8 warps 2(M)x4(N), warp tile 64x64.
// ===========================================================================
#define BK       32
#define PAD      40
#define A_TEH    (128*PAD)
#define B_TEH    (256*PAD)
#define STAGE_H  (A_TEH + B_TEH)
#define PRJ_SMEM (3*STAGE_H*2)      /* 92160 bytes */
#define PRJ_NKT  (DIM/BK)           /* 32 */

__device__ __forceinline__ void gemm1(
    const __half* __restrict__ Ah, const __half* __restrict__ Bh,
    __half* sm, float (&acc)[4][8][4])
{
    const int tid  = threadIdx.x;
    const int warp = tid >> 5, lane = tid & 31;
    const int wm0  = (warp & 1) << 6;
    const int wn0  = (warp >> 1) << 6;
    const int a_row = (lane & 7) + ((lane >> 3) & 1) * 8;
    const int a_k   = ((lane >> 4) & 1) * 8;
    const int b_row = (lane & 7) + ((lane >> 4) & 1) * 8;
    const int b_k   = ((lane >> 3) & 1) * 8;
    const uint32_t sb = smem_u32(sm);

    auto load_stage = [&](int kt, int s) {
        uint32_t st = sb + (uint32_t)s * STAGE_H * 2;
        #pragma unroll
        for (int c = 0; c < 2; ++c) {
            int idx = tid + c * 256;
            int row = idx >> 2, ch = idx & 3;
            cp_async16(st + (uint32_t)(row * PAD + ch * 8) * 2,
                       Ah + (size_t)row * DIM + kt * BK + ch * 8);
        }
        uint32_t bb = st + (uint32_t)A_TEH * 2;
        #pragma unroll
        for (int c = 0; c < 4; ++c) {
            int idx = tid + c * 256;
            int row = idx >> 2, ch = idx & 3;
            cp_async16(bb + (uint32_t)(row * PAD + ch * 8) * 2,
                       Bh + (size_t)row * DIM + kt * BK + ch * 8);
        }
    };

    load_stage(0, 0);
    asm volatile("cp.async.commit_group;\n" ::: "memory");
    load_stage(1, 1);
    asm volatile("cp.async.commit_group;\n" ::: "memory");

    for (int kt = 0; kt < PRJ_NKT; ++kt) {
        const int cur = kt % 3;
        if (kt + 2 < PRJ_NKT) {
            load_stage(kt + 2, (kt + 2) % 3);
            asm volatile("cp.async.commit_group;\n" ::: "memory");
            asm volatile("cp.async.wait_group 2;\n" ::: "memory");
        } else if (kt + 1 < PRJ_NKT) {
            asm volatile("cp.async.wait_group 1;\n" ::: "memory");
        } else {
            asm volatile("cp.async.wait_group 0;\n" ::: "memory");
        }
        __syncthreads();

        const uint32_t st  = sb + (uint32_t)cur * STAGE_H * 2;
        const uint32_t sAh = st;
        const uint32_t sBh = st + A_TEH * 2;

        #pragma unroll
        for (int ks = 0; ks < BK; ks += 16) {
            uint32_t b[8][2];
            #pragma unroll
            for (int jj = 0; jj < 4; ++jj) {
                uint32_t r[4];
                ldsm4(sBh + (uint32_t)((wn0 + jj*16 + b_row) * PAD + ks + b_k) * 2, r);
                b[jj*2+0][0] = r[0]; b[jj*2+0][1] = r[1];
                b[jj*2+1][0] = r[2]; b[jj*2+1][1] = r[3];
            }
            uint32_t af[4][4];
            #pragma unroll
            for (int i = 0; i < 4; ++i)
                ldsm4(sAh + (uint32_t)((wm0 + i*16 + a_row) * PAD + ks + a_k) * 2, af[i]);
            #pragma unroll
            for (int i = 0; i < 4; ++i)
                #pragma unroll
                for (int j = 0; j < 8; ++j) mma16(acc[i][j], af[i], b[j]);
        }
        __syncthreads();
    }
}

// ---- 1) QKV projection: Q hi (scaled by 1/8), K hi, V hi transposed --------
__global__ __launch_bounds__(256, 1) void qkv_mma()
{
    extern __shared__ __half sm[];
    const int z = blockIdx.z;
    const __half* Ah = g_xh + (size_t)blockIdx.y * 128 * DIM;
    const __half* Bh = g_wh + (size_t)z * DIM * DIM + (size_t)blockIdx.x * 256 * DIM;

    float acc[4][8][4] = {};
    gemm1(Ah, Bh, sm, acc);

    const int warp = threadIdx.x >> 5, lane = threadIdx.x & 31;
    const int g = lane >> 2, t2 = (lane & 3) << 1;
    const int wm0 = (warp & 1) << 6, wn0 = (warp >> 1) << 6;
    #pragma unroll
    for (int i = 0; i < 4; ++i)
        #pragma unroll
        for (int j = 0; j < 8; ++j)
            #pragma unroll
            for (int r = 0; r < 4; ++r) {
                int m = blockIdx.y * 128 + wm0 + i * 16 + g + ((r >= 2) ? 8 : 0);
                int n = blockIdx.x * 256 + wn0 + j * 8 + t2 + (r & 1);
                int b = m >> 9, s = m & 511, h = n >> 6, d = n & 63;
                float v = acc[i][j][r];
                if (z == 0) {
                    size_t idx = ((size_t)(b * HEADS + h) * SEQ + s) * HD + d;
                    g_qh[idx] = __float2half(v * 0.125f);
                } else if (z == 1) {
                    size_t idx = ((size_t)(b * HEADS + h) * SEQ + s) * HD + d;
                    g_kh[idx] = __float2half(v);
                } else {
                    size_t idx = ((size_t)(b * HEADS + h) * HD + d) * SEQ + s;
                    g_vh[idx] = __float2half(v);
                }
            }
}

// ---- 5) out projection + bias ----------------------------------------------
__global__ __launch_bounds__(256, 1) void out_mma(const float* __restrict__ bo,
                                                  float* __restrict__ out)
{
    extern __shared__ __half sm[];
    const __half* Ah = g_ch + (size_t)blockIdx.y * 128 * DIM;
    const __half* Bh = g_woh + (size_t)blockIdx.x * 256 * DIM;

    float acc[4][8][4] = {};
    gemm1(Ah, Bh, sm, acc);

    const int warp = threadIdx.x >> 5, lane = threadIdx.x & 31;
    const int g = lane >> 2, t2 = (lane & 3) << 1;
    const int wm0 = (warp & 1) << 6, wn0 = (warp >> 1) << 6;
    #pragma unroll
    for (int i = 0; i < 4; ++i)
        #pragma unroll
        for (int j = 0; j < 8; ++j)
            #pragma unroll
            for (int r = 0; r < 4; ++r) {
                int m = blockIdx.y * 128 + wm0 + i * 16 + g + ((r >= 2) ? 8 : 0);
                int n = blockIdx.x * 256 + wn0 + j * 8 + t2 + (r & 1);
                out[(size_t)m * DIM + n] = acc[i][j][r] + bo[n];
            }
}

// ===========================================================================
//  fused flash attention: 128-thread CTA, 4 warps x 16 q rows (q-tile 64).
//  grid (8 qtiles, 128 bh) -> 1024 CTAs, 2 CTAs/SM.
//  S = Qhi·Khi (1-term), online softmax fp32, O += Phi·Vhi (1-term).
// ===========================================================================
#define FA_PADK 72
#define FA_PADV 136
#define FA_KH   (128*FA_PADK)            /* halves */
#define FA_VT   (64*FA_PADV)
#define FA_STAGE_H (FA_KH + FA_VT)       /* 17920 halves */
#define FA_Q_H  (64*FA_PADK)             /* 4608 halves  */
#define FA_SMEM ((FA_Q_H + 2*FA_STAGE_H)*2)   /* 80896 B */

__global__ __launch_bounds__(128) void flash_attn()
{
    extern __shared__ __half fsm[];
    const int qt = blockIdx.x, bh = blockIdx.y;
    const int tid = threadIdx.x, warp = tid >> 5, lane = tid & 31;
    const int g = lane >> 2, t2 = (lane & 3) << 1;
    const int a_row = (lane & 7) + ((lane >> 3) & 1) * 8;
    const int a_k   = ((lane >> 4) & 1) * 8;
    const int b_row = (lane & 7) + ((lane >> 4) & 1) * 8;
    const int b_k   = ((lane >> 3) & 1) * 8;

    const int NT8[8] = {2, 2, 2, 2, 3, 3, 4, 4};
    const int ntiles = NT8[qt];

    const __half* Qh = g_qh + ((size_t)bh * SEQ + qt * 64) * HD;
    const __half* Kh = g_kh + (size_t)bh * SEQ * HD;
    const __half* Vt = g_vh + (size_t)bh * HD * SEQ;

    const uint32_t sb  = smem_u32(fsm);
    const uint32_t sQh = sb;
    const uint32_t sStg = sb + (uint32_t)FA_Q_H * 2;

    // Q staging: 64 rows x 8 chunks = 512 chunks, 4 per thread
    #pragma unroll
    for (int c = 0; c < 4; ++c) {
        int idx = tid + c * 128;
        int row = idx >> 3, ch = idx & 7;
        cp_async16(sQh + (uint32_t)(row * FA_PADK + ch * 8) * 2, Qh + (size_t)row * HD + ch * 8);
    }
    asm volatile("cp.async.commit_group;\n" ::: "memory");

    auto load_kv = [&](int t, int s) {
        uint32_t st = sStg + (uint32_t)s * FA_STAGE_H * 2;
        // K: 128 rows x 8 chunks = 1024 chunks, 8 per thread
        #pragma unroll
        for (int c = 0; c < 8; ++c) {
            int idx = tid + c * 128;
            int row = idx >> 3, ch = idx & 7;
            cp_async16(st + (uint32_t)(row * FA_PADK + ch * 8) * 2,
                       Kh + (size_t)(t * 128 + row) * HD + ch * 8);
        }
        // V: 64 rows x 16 chunks = 1024 chunks
        uint32_t sv = st + (uint32_t)FA_KH * 2;
        #pragma unroll
        for (int c = 0; c < 8; ++c) {
            int idx = tid + c * 128;
            int row = idx >> 4, ch = idx & 15;
            cp_async16(sv + (uint32_t)(row * FA_PADV + ch * 8) * 2,
                       Vt + (size_t)row * SEQ + t * 128 + ch * 8);
        }
    };

    load_kv(0, 0);
    asm volatile("cp.async.commit_group;\n" ::: "memory");

    asm volatile("cp.async.wait_group 1;\n" ::: "memory");
    __syncthreads();
    uint32_t qfh[4][4];
    #pragma unroll
    for (int ks = 0; ks < 4; ++ks)
        ldsm4(sQh + (uint32_t)((warp * 16 + a_row) * FA_PADK + ks * 16 + a_k) * 2, qfh[ks]);

    float acc_o[8][4] = {};
    float m0 = neg_inf(), m1 = neg_inf(), l0 = 0.f, l1 = 0.f;

    for (int t = 0; t < ntiles; ++t) {
        if (t + 1 < ntiles) {
            load_kv(t + 1, (t + 1) & 1);
            asm volatile("cp.async.commit_group;\n" ::: "memory");
            asm volatile("cp.async.wait_group 1;\n" ::: "memory");
        } else {
            asm volatile("cp.async.wait_group 0;\n" ::: "memory");
        }
        __syncthreads();

        const uint32_t st = sStg + (uint32_t)(t & 1) * FA_STAGE_H * 2;
        const uint32_t sK = st;
        const uint32_t sV = st + (uint32_t)FA_KH * 2;

        // ---- S = Q K^T (1-term), warp tile 16x128 ----
        float s[16][4];
        #pragma unroll
        for (int j = 0; j < 16; ++j)
            #pragma unroll
            for (int r = 0; r < 4; ++r) s[j][r] = 0.f;

        #pragma unroll
        for (int ks = 0; ks < 4; ++ks) {
            uint32_t bfr[16][2];
            #pragma unroll
            for (int jj = 0; jj < 8; ++jj) {
                uint32_t r[4];
                ldsm4(sK + (uint32_t)((jj*16 + b_row) * FA_PADK + ks*16 + b_k) * 2, r);
                bfr[jj*2+0][0] = r[0]; bfr[jj*2+0][1] = r[1];
                bfr[jj*2+1][0] = r[2]; bfr[jj*2+1][1] = r[3];
            }
            #pragma unroll
            for (int j = 0; j < 16; ++j)
                mma16(s[j], qfh[ks], bfr[j]);
        }

        if (t == ntiles - 1) {
            const int q0 = qt * 64 + warp * 16 + g, q1 = q0 + 8;
            #pragma unroll
            for (int j = 0; j < 16; ++j) {
                int k0 = t * 128 + j * 8 + t2;
                if (!okqk(q0, k0))     s[j][0] = neg_inf();
                if (!okqk(q0, k0 + 1)) s[j][1] = neg_inf();
                if (!okqk(q1, k0))     s[j][2] = neg_inf();
                if (!okqk(q1, k0 + 1)) s[j][3] = neg_inf();
            }
        }

        // ---- online softmax ----
        float mx0 = neg_inf(), mx1 = neg_inf();
        #pragma unroll
        for (int j = 0; j < 16; ++j) {
            mx0 = fmaxf(mx0, fmaxf(s[j][0], s[j][1]));
            mx1 = fmaxf(mx1, fmaxf(s[j][2], s[j][3]));
        }
        mx0 = fmaxf(mx0, __shfl_xor_sync(0xffffffffu, mx0, 1));
        mx0 = fmaxf(mx0, __shfl_xor_sync(0xffffffffu, mx0, 2));
        mx1 = fmaxf(mx1, __shfl_xor_sync(0xffffffffu, mx1, 1));
        mx1 = fmaxf(mx1, __shfl_xor_sync(0xffffffffu, mx1, 2));

        const float mn0 = fmaxf(m0, mx0), mn1 = fmaxf(m1, mx1);
        const float sc0 = __expf(m0 - mn0), sc1 = __expf(m1 - mn1);
        m0 = mn0; m1 = mn1;

        float sum0 = 0.f, sum1 = 0.f;
        #pragma unroll
        for (int j = 0; j < 16; ++j) {
            s[j][0] = __expf(s[j][0] - mn0); sum0 += s[j][0];
            s[j][1] = __expf(s[j][1] - mn0); sum0 += s[j][1];
            s[j][2] = __expf(s[j][2] - mn1); sum1 += s[j][2];
            s[j][3] = __expf(s[j][3] - mn1); sum1 += s[j][3];
        }
        sum0 += __shfl_xor_sync(0xffffffffu, sum0, 1);
        sum0 += __shfl_xor_sync(0xffffffffu, sum0, 2);
        sum1 += __shfl_xor_sync(0xffffffffu, sum1, 1);
        sum1 += __shfl_xor_sync(0xffffffffu, sum1, 2);
        l0 = l0 * sc0 + sum0;
        l1 = l1 * sc1 + sum1;

        #pragma unroll
        for (int jn = 0; jn < 8; ++jn) {
            acc_o[jn][0] *= sc0; acc_o[jn][1] *= sc0;
            acc_o[jn][2] *= sc1; acc_o[jn][3] *= sc1;
        }

        // ---- O += P V (P hi only) ----
        #pragma unroll
        for (int ks = 0; ks < 8; ++ks) {
            uint32_t bv[8][2];
            #pragma unroll
            for (int jj = 0; jj < 4; ++jj) {
                uint32_t r[4];
                ldsm4(sV + (uint32_t)((jj*16 + b_row) * FA_PADV + ks*16 + b_k) * 2, r);
                bv[jj*2+0][0] = r[0]; bv[jj*2+0][1] = r[1];
                bv[jj*2+1][0] = r[2]; bv[jj*2+1][1] = r[3];
            }
            uint32_t pah[4];
            #pragma unroll
            for (int half = 0; half < 2; ++half) {
                const float* ps = s[2*ks + half];
                __half2 ah  = __halves2half2(__float2half(ps[0]), __float2half(ps[1]));
                __half2 bhv = __halves2half2(__float2half(ps[2]), __float2half(ps[3]));
                pah[half*2+0] = *reinterpret_cast<uint32_t*>(&ah);
                pah[half*2+1] = *reinterpret_cast<uint32_t*>(&bhv);
            }
            #pragma unroll
            for (int jn = 0; jn < 8; ++jn)
                mma16(acc_o[jn], pah, bv[jn]);
        }
        __syncthreads();
    }

    const float il0 = __frcp_rn(l0), il1 = __frcp_rn(l1);
    const int b = bh >> 4, h = bh & 15;
    const int q0 = qt * 64 + warp * 16 + g;
    #pragma unroll
    for (int jn = 0; jn < 8; ++jn)
        #pragma unroll
        for (int r = 0; r < 4; ++r) {
            int q = (r >= 2) ? q0 + 8 : q0;
            float v = acc_o[jn][r] * ((r >= 2) ? il1 : il0);
            int n = jn * 8 + t2 + (r & 1);
            size_t idx = ((size_t)(b * SEQ + q) * DIM) + h * HD + n;
            g_ch[idx] = __float2half(v);
        }
}

// ===========================================================================
extern "C" void kernel_launch(void* const* d_in, const int* in_sizes, int n_in,
                              void* d_out, int out_size)
{
    const float* x  = (const float*)d_in[0];
    const float* wq = (const float*)d_in[1];
    const float* wk = (const float*)d_in[2];
    const float* wv = (const float*)d_in[3];
    const float* wo = (const float*)d_in[4];
    const float* bo = (const float*)d_in[5];
    float* out = (float*)d_out;

    static bool attr_set = false;
    if (!attr_set) {
        cudaFuncSetAttribute(qkv_mma,    cudaFuncAttributeMaxDynamicSharedMemorySize, PRJ_SMEM);
        cudaFuncSetAttribute(out_mma,    cudaFuncAttributeMaxDynamicSharedMemorySize, PRJ_SMEM);
        cudaFuncSetAttribute(flash_attn, cudaFuncAttributeMaxDynamicSharedMemorySize, FA_SMEM);
        attr_set = true;
    }

    split_all<<<4096 + 4*1024, 256>>>(x, wq, wk, wv, wo);

    qkv_mma   <<<dim3(DIM/256, MROWS/128, 3), 256, PRJ_SMEM>>>();
    flash_attn<<<dim3(SEQ/64, BH), 128, FA_SMEM>>>();
    out_mma   <<<dim3(DIM/256, MROWS/128), 256, PRJ_SMEM>>>(bo, out);
}